// round 1
// baseline (speedup 1.0000x reference)
#include <cuda_runtime.h>
#include <math.h>

#define D_MODEL 1024
#define BATCH   2
#define TQ      2048
#define SKV     4096
#define NHEADS  16
#define HDIM    64

// Scratch (no cudaMalloc allowed): Q, K, V projections + attention output Y.
__device__ float g_Q[(size_t)BATCH * TQ  * D_MODEL];   // 16 MB
__device__ float g_K[(size_t)BATCH * SKV * D_MODEL];   // 32 MB
__device__ float g_V[(size_t)BATCH * SKV * D_MODEL];   // 32 MB
__device__ float g_Y[(size_t)BATCH * TQ  * D_MODEL];   // 16 MB

// ---------------------------------------------------------------------------
// NT GEMM: C[m][n] = sum_k A[m][k] * B[n][k]
// A row-major [M,K], B row-major [N,K] (nn.Linear weight), C row-major [M,N].
// 128x128 block tile, BK=8, 256 threads, 8x8 per thread (4+4 split),
// k-major smem tiles with stride 132 (conflict-free fill and fragment loads).
// M, N multiples of 128; K multiple of 8.
// ---------------------------------------------------------------------------
__global__ __launch_bounds__(256, 2)
void gemm_nt_kernel(const float* __restrict__ A, const float* __restrict__ B,
                    float* __restrict__ C, int M, int N, int K) {
  __shared__ __align__(16) float As[8][132];
  __shared__ __align__(16) float Bs[8][132];

  const int tid = threadIdx.x;
  const int ty = tid >> 4;        // 0..15
  const int tx = tid & 15;        // 0..15
  const int bm = blockIdx.y * 128;
  const int bn = blockIdx.x * 128;

  const int lr = tid >> 1;        // 0..127  (tile row loaded by this thread)
  const int lk = (tid & 1) * 4;   // 0 or 4  (k offset, float4)

  const float* Ap = A + (size_t)(bm + lr) * K + lk;
  const float* Bp = B + (size_t)(bn + lr) * K + lk;

  float acc[8][8];
#pragma unroll
  for (int i = 0; i < 8; i++)
#pragma unroll
    for (int j = 0; j < 8; j++) acc[i][j] = 0.0f;

  for (int k0 = 0; k0 < K; k0 += 8) {
    float4 av = *(const float4*)(Ap + k0);
    float4 bv = *(const float4*)(Bp + k0);
    As[lk + 0][lr] = av.x; As[lk + 1][lr] = av.y;
    As[lk + 2][lr] = av.z; As[lk + 3][lr] = av.w;
    Bs[lk + 0][lr] = bv.x; Bs[lk + 1][lr] = bv.y;
    Bs[lk + 2][lr] = bv.z; Bs[lk + 3][lr] = bv.w;
    __syncthreads();

#pragma unroll
    for (int k = 0; k < 8; k++) {
      float a[8], b[8];
      *(float4*)&a[0] = *(const float4*)&As[k][4 * ty];
      *(float4*)&a[4] = *(const float4*)&As[k][64 + 4 * ty];
      *(float4*)&b[0] = *(const float4*)&Bs[k][4 * tx];
      *(float4*)&b[4] = *(const float4*)&Bs[k][64 + 4 * tx];
#pragma unroll
      for (int i = 0; i < 8; i++)
#pragma unroll
        for (int j = 0; j < 8; j++) acc[i][j] += a[i] * b[j];
    }
    __syncthreads();
  }

#pragma unroll
  for (int i = 0; i < 8; i++) {
    int r = bm + ((i < 4) ? (4 * ty + i) : (64 + 4 * ty + i - 4));
    float4 v0 = make_float4(acc[i][0], acc[i][1], acc[i][2], acc[i][3]);
    float4 v1 = make_float4(acc[i][4], acc[i][5], acc[i][6], acc[i][7]);
    *(float4*)(C + (size_t)r * N + bn + 4 * tx)      = v0;
    *(float4*)(C + (size_t)r * N + bn + 64 + 4 * tx) = v1;
  }
}

// ---------------------------------------------------------------------------
// Flash attention (fp32, online softmax), per (b, h, q-tile of 64).
// Scores tile 64x64; 256 threads as 16x16, each owning a 4x4 micro-tile.
// Mask: + log(clip(imp[b, key % 16], 1e-6)); scale 1/sqrt(64) = 0.125.
// Dynamic smem: Qs[64][65] + Ks[64][65] + Ps[64][65] + Vs[64][68].
// ---------------------------------------------------------------------------
#define FLASH_SMEM_FLOATS (3 * 64 * 65 + 64 * 68)
#define FLASH_SMEM_BYTES  (FLASH_SMEM_FLOATS * 4)

__global__ __launch_bounds__(256, 2)
void flash_kernel(const float* __restrict__ Qm, const float* __restrict__ Km,
                  const float* __restrict__ Vm, const float* __restrict__ imp,
                  float* __restrict__ Y) {
  extern __shared__ __align__(16) float sm[];
  float* Qs = sm;                    // [dim 64][row 64], stride 65 (k-major)
  float* Ks = sm + 64 * 65;          // [dim 64][key 64], stride 65 (k-major)
  float* Ps = sm + 2 * 64 * 65;      // [row 64][key 64], stride 65
  float* Vs = sm + 3 * 64 * 65;      // [key 64][dim 64], stride 68 (row-major)

  const int b  = blockIdx.z;
  const int h  = blockIdx.y;
  const int q0 = blockIdx.x * 64;
  const int tid = threadIdx.x;
  const int ty = tid >> 4;           // 0..15 -> rows 4*ty..4*ty+3
  const int tx = tid & 15;           // 0..15 -> cols 4*tx..4*tx+3

  const float* Qh = Qm + ((size_t)b * TQ + q0) * D_MODEL + h * HDIM;
  const float* Kh = Km + (size_t)b * SKV * D_MODEL + h * HDIM;
  const float* Vh = Vm + (size_t)b * SKV * D_MODEL + h * HDIM;

  // Fill Q tile transposed (k-major).
  {
    const int r0 = tid >> 4;
    const int k4 = (tid & 15) * 4;
#pragma unroll
    for (int it = 0; it < 4; it++) {
      int r = r0 + it * 16;
      float4 v = *(const float4*)(Qh + (size_t)r * D_MODEL + k4);
      Qs[(k4 + 0) * 65 + r] = v.x;
      Qs[(k4 + 1) * 65 + r] = v.y;
      Qs[(k4 + 2) * 65 + r] = v.z;
      Qs[(k4 + 3) * 65 + r] = v.w;
    }
  }

  // Additive mask for this thread's 4 key columns (tile-position invariant:
  // key % 16 == (4*tx + j) % 16 because tiles start at multiples of 64).
  float lgj[4];
#pragma unroll
  for (int j = 0; j < 4; j++)
    lgj[j] = logf(fmaxf(imp[b * NHEADS + ((4 * tx + j) & 15)], 1e-6f));

  float m_i[4], l_i[4], acc[4][4];
#pragma unroll
  for (int i = 0; i < 4; i++) {
    m_i[i] = -INFINITY;
    l_i[i] = 0.0f;
#pragma unroll
    for (int j = 0; j < 4; j++) acc[i][j] = 0.0f;
  }

  for (int s0 = 0; s0 < SKV; s0 += 64) {
    __syncthreads();  // previous iteration done with Ks/Vs/Ps; Qs ready (1st iter)

    // Fill K tile (transposed, k-major) and V tile (row-major).
    {
      const int r0 = tid >> 4;
      const int k4 = (tid & 15) * 4;
#pragma unroll
      for (int it = 0; it < 4; it++) {
        int key = r0 + it * 16;
        float4 kv = *(const float4*)(Kh + (size_t)(s0 + key) * D_MODEL + k4);
        Ks[(k4 + 0) * 65 + key] = kv.x;
        Ks[(k4 + 1) * 65 + key] = kv.y;
        Ks[(k4 + 2) * 65 + key] = kv.z;
        Ks[(k4 + 3) * 65 + key] = kv.w;
        float4 vv = *(const float4*)(Vh + (size_t)(s0 + key) * D_MODEL + k4);
        *(float4*)&Vs[key * 68 + k4] = vv;
      }
    }
    __syncthreads();

    // S = Q K^T (4x4 per thread, rank-1 updates over dim k).
    float s[4][4];
#pragma unroll
    for (int i = 0; i < 4; i++)
#pragma unroll
      for (int j = 0; j < 4; j++) s[i][j] = 0.0f;

#pragma unroll 16
    for (int k = 0; k < 64; k++) {
      float a0 = Qs[k * 65 + 4 * ty + 0];
      float a1 = Qs[k * 65 + 4 * ty + 1];
      float a2 = Qs[k * 65 + 4 * ty + 2];
      float a3 = Qs[k * 65 + 4 * ty + 3];
      float b0 = Ks[k * 65 + 4 * tx + 0];
      float b1 = Ks[k * 65 + 4 * tx + 1];
      float b2 = Ks[k * 65 + 4 * tx + 2];
      float b3 = Ks[k * 65 + 4 * tx + 3];
      s[0][0] += a0 * b0; s[0][1] += a0 * b1; s[0][2] += a0 * b2; s[0][3] += a0 * b3;
      s[1][0] += a1 * b0; s[1][1] += a1 * b1; s[1][2] += a1 * b2; s[1][3] += a1 * b3;
      s[2][0] += a2 * b0; s[2][1] += a2 * b1; s[2][2] += a2 * b2; s[2][3] += a2 * b3;
      s[3][0] += a3 * b0; s[3][1] += a3 * b1; s[3][2] += a3 * b2; s[3][3] += a3 * b3;
    }

    // scale + mask; row max over 4 local cols then across 16-lane tx group.
    float mt[4];
#pragma unroll
    for (int i = 0; i < 4; i++) {
      float mm = -INFINITY;
#pragma unroll
      for (int j = 0; j < 4; j++) {
        s[i][j] = s[i][j] * 0.125f + lgj[j];
        mm = fmaxf(mm, s[i][j]);
      }
#pragma unroll
      for (int off = 8; off; off >>= 1)
        mm = fmaxf(mm, __shfl_xor_sync(0xffffffffu, mm, off));
      mt[i] = mm;
    }

    // Online softmax update; write P to smem; accumulate row sums.
    float rs[4];
#pragma unroll
    for (int i = 0; i < 4; i++) {
      float mnew = fmaxf(m_i[i], mt[i]);
      float corr = __expf(m_i[i] - mnew);
      float r = 0.0f;
#pragma unroll
      for (int j = 0; j < 4; j++) {
        float p = __expf(s[i][j] - mnew);
        Ps[(4 * ty + i) * 65 + 4 * tx + j] = p;
        r += p;
      }
#pragma unroll
      for (int off = 8; off; off >>= 1)
        r += __shfl_xor_sync(0xffffffffu, r, off);
      rs[i] = r;
      l_i[i] = l_i[i] * corr + r;
      m_i[i] = mnew;
#pragma unroll
      for (int j = 0; j < 4; j++) acc[i][j] *= corr;
    }
    (void)rs;
    __syncthreads();  // P visible to all

    // O += P @ V
#pragma unroll 8
    for (int kk = 0; kk < 64; kk++) {
      float p0 = Ps[(4 * ty + 0) * 65 + kk];
      float p1 = Ps[(4 * ty + 1) * 65 + kk];
      float p2 = Ps[(4 * ty + 2) * 65 + kk];
      float p3 = Ps[(4 * ty + 3) * 65 + kk];
      float4 v = *(const float4*)&Vs[kk * 68 + 4 * tx];
      acc[0][0] += p0 * v.x; acc[0][1] += p0 * v.y; acc[0][2] += p0 * v.z; acc[0][3] += p0 * v.w;
      acc[1][0] += p1 * v.x; acc[1][1] += p1 * v.y; acc[1][2] += p1 * v.z; acc[1][3] += p1 * v.w;
      acc[2][0] += p2 * v.x; acc[2][1] += p2 * v.y; acc[2][2] += p2 * v.z; acc[2][3] += p2 * v.w;
      acc[3][0] += p3 * v.x; acc[3][1] += p3 * v.y; acc[3][2] += p3 * v.z; acc[3][3] += p3 * v.w;
    }
  }

  // Epilogue: normalize and store merged-head layout Y[b, q, h*64 + dim].
#pragma unroll
  for (int i = 0; i < 4; i++) {
    float inv = 1.0f / l_i[i];
    int r = q0 + 4 * ty + i;
    float4 o = make_float4(acc[i][0] * inv, acc[i][1] * inv,
                           acc[i][2] * inv, acc[i][3] * inv);
    *(float4*)(Y + ((size_t)b * TQ + r) * D_MODEL + h * HDIM + 4 * tx) = o;
  }
}

// ---------------------------------------------------------------------------
extern "C" void kernel_launch(void* const* d_in, const int* in_sizes, int n_in,
                              void* d_out, int out_size) {
  const float* query     = (const float*)d_in[0];  // [2,2048,1024]
  const float* key_value = (const float*)d_in[1];  // [2,256,16,1024] == [2,4096,1024]
  const float* imp       = (const float*)d_in[2];  // [2,16]
  const float* Wq        = (const float*)d_in[3];  // [1024,1024]
  const float* Wk        = (const float*)d_in[4];
  const float* Wv        = (const float*)d_in[5];
  const float* Wo        = (const float*)d_in[6];
  float* out = (float*)d_out;                      // [2,2048,1024]

  float *Qb, *Kb, *Vb, *Yb;
  cudaGetSymbolAddress((void**)&Qb, g_Q);
  cudaGetSymbolAddress((void**)&Kb, g_K);
  cudaGetSymbolAddress((void**)&Vb, g_V);
  cudaGetSymbolAddress((void**)&Yb, g_Y);

  cudaFuncSetAttribute(flash_kernel,
                       cudaFuncAttributeMaxDynamicSharedMemorySize,
                       FLASH_SMEM_BYTES);

  dim3 blk(256);
  // Projections (kv reshape is a no-op: [B, T_kv*N_s, D] is already contiguous).
  gemm_nt_kernel<<<dim3(8, 32), blk>>>(query,     Wq, Qb, BATCH * TQ,  D_MODEL, D_MODEL);
  gemm_nt_kernel<<<dim3(8, 64), blk>>>(key_value, Wk, Kb, BATCH * SKV, D_MODEL, D_MODEL);
  gemm_nt_kernel<<<dim3(8, 64), blk>>>(key_value, Wv, Vb, BATCH * SKV, D_MODEL, D_MODEL);

  // Attention with importance mask + online softmax.
  flash_kernel<<<dim3(TQ / 64, NHEADS, BATCH), blk, FLASH_SMEM_BYTES>>>(Qb, Kb, Vb, imp, Yb);

  // Output projection straight into d_out.
  gemm_nt_kernel<<<dim3(8, 32), blk>>>(Yb, Wo, out, BATCH * TQ, D_MODEL, D_MODEL);
}

// round 3
// speedup vs baseline: 1.2110x; 1.2110x over previous
#include <cuda_runtime.h>
#include <cuda_bf16.h>
#include <cstdint>
#include <math.h>

#define D_MODEL 1024
#define BATCH   2
#define TQ      2048
#define SKV     4096
#define NHEADS  16
#define HDIM    64

// ---------------- scratch (no cudaMalloc allowed) ----------------
__device__ float g_Q[(size_t)BATCH * TQ  * D_MODEL];
__device__ float g_K[(size_t)BATCH * SKV * D_MODEL];
__device__ float g_V[(size_t)BATCH * SKV * D_MODEL];
__device__ float g_Y[(size_t)BATCH * TQ  * D_MODEL];

__device__ __nv_bfloat16 g_qh[(size_t)BATCH * TQ  * D_MODEL];
__device__ __nv_bfloat16 g_ql[(size_t)BATCH * TQ  * D_MODEL];
__device__ __nv_bfloat16 g_kvh[(size_t)BATCH * SKV * D_MODEL];
__device__ __nv_bfloat16 g_kvl[(size_t)BATCH * SKV * D_MODEL];
__device__ __nv_bfloat16 g_yh[(size_t)BATCH * TQ  * D_MODEL];
__device__ __nv_bfloat16 g_yl[(size_t)BATCH * TQ  * D_MODEL];
__device__ __nv_bfloat16 g_wh[4][(size_t)D_MODEL * D_MODEL];
__device__ __nv_bfloat16 g_wl[4][(size_t)D_MODEL * D_MODEL];

// ---------------- portable sm_80+ primitives ----------------
__device__ __forceinline__ uint32_t smem_u32(const void* p) {
  uint32_t a;
  asm("{ .reg .u64 t; cvta.to.shared.u64 t, %1; cvt.u32.u64 %0, t; }"
      : "=r"(a) : "l"(p));
  return a;
}
__device__ __forceinline__ void ldsm4(uint32_t* r, uint32_t a) {
  asm volatile("ldmatrix.sync.aligned.m8n8.x4.shared.b16 {%0,%1,%2,%3}, [%4];"
               : "=r"(r[0]), "=r"(r[1]), "=r"(r[2]), "=r"(r[3]) : "r"(a));
}
__device__ __forceinline__ void mma16816(float* d, const uint32_t* a,
                                         const uint32_t* b) {
  asm volatile(
      "mma.sync.aligned.m16n8k16.row.col.f32.bf16.bf16.f32 "
      "{%0,%1,%2,%3}, {%4,%5,%6,%7}, {%8,%9}, {%0,%1,%2,%3};"
      : "+f"(d[0]), "+f"(d[1]), "+f"(d[2]), "+f"(d[3])
      : "r"(a[0]), "r"(a[1]), "r"(a[2]), "r"(a[3]), "r"(b[0]), "r"(b[1]));
}
__device__ __forceinline__ void cp16(uint32_t dst, const void* src) {
  asm volatile("cp.async.cg.shared.global [%0], [%1], 16;" :: "r"(dst), "l"(src));
}
#define CP_COMMIT() asm volatile("cp.async.commit_group;")

// ---------------------------------------------------------------------------
// f32 -> (bf16 hi, bf16 lo) split conversion. n multiple of 1024.
// ---------------------------------------------------------------------------
__global__ void cvt_bf16x2_kernel(const float* __restrict__ x,
                                  __nv_bfloat16* __restrict__ hi,
                                  __nv_bfloat16* __restrict__ lo, int n) {
  int i = (blockIdx.x * blockDim.x + threadIdx.x) * 4;
  if (i >= n) return;
  float4 v = *(const float4*)(x + i);
  __nv_bfloat16 h0 = __float2bfloat16(v.x);
  __nv_bfloat16 h1 = __float2bfloat16(v.y);
  __nv_bfloat16 h2 = __float2bfloat16(v.z);
  __nv_bfloat16 h3 = __float2bfloat16(v.w);
  __nv_bfloat16 l0 = __float2bfloat16(v.x - __bfloat162float(h0));
  __nv_bfloat16 l1 = __float2bfloat16(v.y - __bfloat162float(h1));
  __nv_bfloat16 l2 = __float2bfloat16(v.z - __bfloat162float(h2));
  __nv_bfloat16 l3 = __float2bfloat16(v.w - __bfloat162float(h3));
  reinterpret_cast<__nv_bfloat162*>(hi + i)[0] = __halves2bfloat162(h0, h1);
  reinterpret_cast<__nv_bfloat162*>(hi + i)[1] = __halves2bfloat162(h2, h3);
  reinterpret_cast<__nv_bfloat162*>(lo + i)[0] = __halves2bfloat162(l0, l1);
  reinterpret_cast<__nv_bfloat162*>(lo + i)[1] = __halves2bfloat162(l2, l3);
}

// ---------------------------------------------------------------------------
// bf16x3 NT GEMM on mma.sync (HMMA): C[m][n] = sum_k A[m][k]*B[n][k], fp32.
// Block tile 128x128, BK=32, 8 warps (4m x 2n) each m32 x n64.
// Passes AhBh + AhBl + AlBh accumulate in fp32.
// Double-buffered smem via cp.async. M%128==0, N%128==0, K%32==0.
// smem halves stride 40 (80B rows -> conflict-free ldmatrix).
// ---------------------------------------------------------------------------
#define GST 40                       // half stride per smem row
#define GTILE_HALFS (128 * GST)      // 5120 halves per tile
#define GTILE_BYTES (GTILE_HALFS * 2)
#define GSTAGE_BYTES (4 * GTILE_BYTES)     // Ah, Al, Bh, Bl
#define GSMEM_BYTES (2 * GSTAGE_BYTES)     // 81920

__global__ __launch_bounds__(256, 2)
void gemm_hmma_bf16x3(const __nv_bfloat16* __restrict__ Ah,
                      const __nv_bfloat16* __restrict__ Al,
                      const __nv_bfloat16* __restrict__ Bh,
                      const __nv_bfloat16* __restrict__ Bl,
                      float* __restrict__ C, int M, int N, int K) {
  extern __shared__ __align__(16) __nv_bfloat16 gsm[];
  const uint32_t sbase = smem_u32(gsm);
  const int tid = threadIdx.x, lane = tid & 31, warp = tid >> 5;
  const int wm = (warp & 3) * 32;
  const int wn = (warp >> 2) * 64;
  const int bm = blockIdx.y * 128;
  const int bn = blockIdx.x * 128;

  float acc[2][8][4];
#pragma unroll
  for (int mi = 0; mi < 2; mi++)
#pragma unroll
    for (int nj = 0; nj < 8; nj++)
#pragma unroll
      for (int q = 0; q < 4; q++) acc[mi][nj][q] = 0.0f;

#define LOAD_CHUNK(kc, stage) do {                                          \
    int kof_ = (kc) << 5;                                                   \
    _Pragma("unroll")                                                       \
    for (int j_ = 0; j_ < 2; j_++) {                                        \
      int idx_ = tid + j_ * 256;                                            \
      int r_ = idx_ >> 2, s_ = (idx_ & 3) * 8;                              \
      size_t ga_ = (size_t)(bm + r_) * K + kof_ + s_;                       \
      size_t gb_ = (size_t)(bn + r_) * K + kof_ + s_;                       \
      uint32_t d_ = sbase + (uint32_t)(stage) * GSTAGE_BYTES +              \
                    (uint32_t)(r_ * GST + s_) * 2;                          \
      cp16(d_,                   Ah + ga_);                                 \
      cp16(d_ + 1 * GTILE_BYTES, Al + ga_);                                 \
      cp16(d_ + 2 * GTILE_BYTES, Bh + gb_);                                 \
      cp16(d_ + 3 * GTILE_BYTES, Bl + gb_);                                 \
    }                                                                       \
  } while (0)

  const int nch = K >> 5;
  LOAD_CHUNK(0, 0);
  CP_COMMIT();

  const int ar = lane & 15;
  const int ac = ((lane >> 4) & 1) * 8;
  const int nof = ((lane >> 4) & 1) * 8 + (lane & 7);
  const int kof2 = ((lane >> 3) & 1) * 8;

  for (int c = 0; c < nch; c++) {
    const int cur = c & 1;
    if (c + 1 < nch) {
      LOAD_CHUNK(c + 1, cur ^ 1);
      CP_COMMIT();
      asm volatile("cp.async.wait_group 1;");
    } else {
      asm volatile("cp.async.wait_group 0;");
    }
    __syncthreads();

    const uint32_t st = sbase + (uint32_t)cur * GSTAGE_BYTES;
#pragma unroll
    for (int ks = 0; ks < 2; ks++) {
      const int k0 = ks * 16;
      uint32_t afh[2][4], afl[2][4];
#pragma unroll
      for (int mi = 0; mi < 2; mi++) {
        uint32_t ad = st + (uint32_t)((wm + mi * 16 + ar) * GST + k0 + ac) * 2;
        ldsm4(afh[mi], ad);
        ldsm4(afl[mi], ad + GTILE_BYTES);
      }
#pragma unroll
      for (int ni = 0; ni < 4; ni++) {
        uint32_t bd = st + 2 * GTILE_BYTES +
                      (uint32_t)((wn + ni * 16 + nof) * GST + k0 + kof2) * 2;
        uint32_t bh[4], bl[4];
        ldsm4(bh, bd);
        ldsm4(bl, bd + GTILE_BYTES);
#pragma unroll
        for (int mi = 0; mi < 2; mi++)
#pragma unroll
          for (int hhalf = 0; hhalf < 2; hhalf++) {
            int nj = ni * 2 + hhalf;
            mma16816(acc[mi][nj], afh[mi], &bh[2 * hhalf]);  // Ah*Bh
            mma16816(acc[mi][nj], afh[mi], &bl[2 * hhalf]);  // Ah*Bl
            mma16816(acc[mi][nj], afl[mi], &bh[2 * hhalf]);  // Al*Bh
          }
      }
    }
    __syncthreads();
  }

  // Epilogue: accumulator layout -> C.
  const int crow = lane >> 2;
  const int ccol = (lane & 3) * 2;
#pragma unroll
  for (int mi = 0; mi < 2; mi++)
#pragma unroll
    for (int nj = 0; nj < 8; nj++) {
      int r0 = bm + wm + mi * 16 + crow;
      int cc = bn + wn + nj * 8 + ccol;
      *(float2*)(C + (size_t)r0 * N + cc) =
          make_float2(acc[mi][nj][0], acc[mi][nj][1]);
      *(float2*)(C + (size_t)(r0 + 8) * N + cc) =
          make_float2(acc[mi][nj][2], acc[mi][nj][3]);
    }
}

// ---------------------------------------------------------------------------
// Flash attention (fp32, online softmax). BQ=64, BS=64, 256 threads 16x16,
// 4x4 micro-tiles. Smem-traffic fixed: Qs/Ks stride 68 (16B-aligned rows,
// float4 fragment loads), transposed fills (conflict-free k-major stores).
// Ps stays stride 65 (broadcast scalar loads).
// ---------------------------------------------------------------------------
#define SQK 68
#define SPP 65
#define SVV 68
#define FLASH_SMEM_FLOATS (64 * SQK * 2 + 64 * SPP + 64 * SVV)
#define FLASH_SMEM_BYTES  (FLASH_SMEM_FLOATS * 4)

__global__ __launch_bounds__(256, 2)
void flash_kernel(const float* __restrict__ Qm, const float* __restrict__ Km,
                  const float* __restrict__ Vm, const float* __restrict__ imp,
                  float* __restrict__ Y) {
  extern __shared__ __align__(16) float sm[];
  float* Qs = sm;                        // [k 64][row 64] stride 68
  float* Ks = sm + 64 * SQK;             // [k 64][key 64] stride 68
  float* Ps = sm + 2 * 64 * SQK;         // [row 64][key 64] stride 65
  float* Vs = sm + 2 * 64 * SQK + 64 * SPP;  // [key 64][dim 64] stride 68

  const int b  = blockIdx.z;
  const int h  = blockIdx.y;
  const int q0 = blockIdx.x * 64;
  const int tid = threadIdx.x;
  const int ty = tid >> 4;
  const int tx = tid & 15;

  const float* Qh = Qm + ((size_t)b * TQ + q0) * D_MODEL + h * HDIM;
  const float* Kh = Km + (size_t)b * SKV * D_MODEL + h * HDIM;
  const float* Vh = Vm + (size_t)b * SKV * D_MODEL + h * HDIM;

  // Fill coords: this thread owns k-rows kq4..kq4+3 for 4 row/key values.
  const int kq4 = (tid >> 4) * 4;  // 0..60
  const int rr0 = tid & 15;

  // Q tile transposed fill (k-major), conflict-free stores.
#pragma unroll
  for (int it = 0; it < 4; it++) {
    int r = rr0 + it * 16;
    float4 v = *(const float4*)(Qh + (size_t)r * D_MODEL + kq4);
    Qs[(kq4 + 0) * SQK + r] = v.x;
    Qs[(kq4 + 1) * SQK + r] = v.y;
    Qs[(kq4 + 2) * SQK + r] = v.z;
    Qs[(kq4 + 3) * SQK + r] = v.w;
  }

  float lgj[4];
#pragma unroll
  for (int j = 0; j < 4; j++)
    lgj[j] = logf(fmaxf(imp[b * NHEADS + ((4 * tx + j) & 15)], 1e-6f));

  float m_i[4], l_i[4], acc[4][4];
#pragma unroll
  for (int i = 0; i < 4; i++) {
    m_i[i] = -INFINITY;
    l_i[i] = 0.0f;
#pragma unroll
    for (int j = 0; j < 4; j++) acc[i][j] = 0.0f;
  }

  for (int s0 = 0; s0 < SKV; s0 += 64) {
    __syncthreads();
    // K transposed fill + V row-major fill.
#pragma unroll
    for (int it = 0; it < 4; it++) {
      int key = rr0 + it * 16;
      float4 kv = *(const float4*)(Kh + (size_t)(s0 + key) * D_MODEL + kq4);
      Ks[(kq4 + 0) * SQK + key] = kv.x;
      Ks[(kq4 + 1) * SQK + key] = kv.y;
      Ks[(kq4 + 2) * SQK + key] = kv.z;
      Ks[(kq4 + 3) * SQK + key] = kv.w;
      float4 vv = *(const float4*)(Vh + (size_t)(s0 + key) * D_MODEL + kq4);
      *(float4*)&Vs[key * SVV + kq4] = vv;
    }
    __syncthreads();

    // S = Q K^T with vectorized fragment loads.
    float s[4][4];
#pragma unroll
    for (int i = 0; i < 4; i++)
#pragma unroll
      for (int j = 0; j < 4; j++) s[i][j] = 0.0f;

#pragma unroll 16
    for (int k = 0; k < 64; k++) {
      float4 a = *(const float4*)&Qs[k * SQK + 4 * ty];
      float4 bb = *(const float4*)&Ks[k * SQK + 4 * tx];
      s[0][0] += a.x * bb.x; s[0][1] += a.x * bb.y; s[0][2] += a.x * bb.z; s[0][3] += a.x * bb.w;
      s[1][0] += a.y * bb.x; s[1][1] += a.y * bb.y; s[1][2] += a.y * bb.z; s[1][3] += a.y * bb.w;
      s[2][0] += a.z * bb.x; s[2][1] += a.z * bb.y; s[2][2] += a.z * bb.z; s[2][3] += a.z * bb.w;
      s[3][0] += a.w * bb.x; s[3][1] += a.w * bb.y; s[3][2] += a.w * bb.z; s[3][3] += a.w * bb.w;
    }

    float mt[4];
#pragma unroll
    for (int i = 0; i < 4; i++) {
      float mm = -INFINITY;
#pragma unroll
      for (int j = 0; j < 4; j++) {
        s[i][j] = s[i][j] * 0.125f + lgj[j];
        mm = fmaxf(mm, s[i][j]);
      }
#pragma unroll
      for (int off = 8; off; off >>= 1)
        mm = fmaxf(mm, __shfl_xor_sync(0xffffffffu, mm, off));
      mt[i] = mm;
    }

#pragma unroll
    for (int i = 0; i < 4; i++) {
      float mnew = fmaxf(m_i[i], mt[i]);
      float corr = __expf(m_i[i] - mnew);
      float r = 0.0f;
#pragma unroll
      for (int j = 0; j < 4; j++) {
        float p = __expf(s[i][j] - mnew);
        Ps[(4 * ty + i) * SPP + 4 * tx + j] = p;
        r += p;
      }
#pragma unroll
      for (int off = 8; off; off >>= 1)
        r += __shfl_xor_sync(0xffffffffu, r, off);
      l_i[i] = l_i[i] * corr + r;
      m_i[i] = mnew;
#pragma unroll
      for (int j = 0; j < 4; j++) acc[i][j] *= corr;
    }
    __syncthreads();

    // O += P @ V  (p: broadcast scalar loads; v: float4)
#pragma unroll 8
    for (int kk = 0; kk < 64; kk++) {
      float p0 = Ps[(4 * ty + 0) * SPP + kk];
      float p1 = Ps[(4 * ty + 1) * SPP + kk];
      float p2 = Ps[(4 * ty + 2) * SPP + kk];
      float p3 = Ps[(4 * ty + 3) * SPP + kk];
      float4 v = *(const float4*)&Vs[kk * SVV + 4 * tx];
      acc[0][0] += p0 * v.x; acc[0][1] += p0 * v.y; acc[0][2] += p0 * v.z; acc[0][3] += p0 * v.w;
      acc[1][0] += p1 * v.x; acc[1][1] += p1 * v.y; acc[1][2] += p1 * v.z; acc[1][3] += p1 * v.w;
      acc[2][0] += p2 * v.x; acc[2][1] += p2 * v.y; acc[2][2] += p2 * v.z; acc[2][3] += p2 * v.w;
      acc[3][0] += p3 * v.x; acc[3][1] += p3 * v.y; acc[3][2] += p3 * v.z; acc[3][3] += p3 * v.w;
    }
  }

#pragma unroll
  for (int i = 0; i < 4; i++) {
    float inv = 1.0f / l_i[i];
    int r = q0 + 4 * ty + i;
    float4 o = make_float4(acc[i][0] * inv, acc[i][1] * inv,
                           acc[i][2] * inv, acc[i][3] * inv);
    *(float4*)(Y + ((size_t)b * TQ + r) * D_MODEL + h * HDIM + 4 * tx) = o;
  }
}

// ---------------------------------------------------------------------------
extern "C" void kernel_launch(void* const* d_in, const int* in_sizes, int n_in,
                              void* d_out, int out_size) {
  const float* query     = (const float*)d_in[0];  // [2,2048,1024]
  const float* key_value = (const float*)d_in[1];  // [2,256,16,1024] == [2,4096,1024]
  const float* imp       = (const float*)d_in[2];  // [2,16]
  const float* Wq        = (const float*)d_in[3];
  const float* Wk        = (const float*)d_in[4];
  const float* Wv        = (const float*)d_in[5];
  const float* Wo        = (const float*)d_in[6];
  float* out = (float*)d_out;                      // [2,2048,1024]

  float *Qb, *Kb, *Vb, *Yb;
  cudaGetSymbolAddress((void**)&Qb, g_Q);
  cudaGetSymbolAddress((void**)&Kb, g_K);
  cudaGetSymbolAddress((void**)&Vb, g_V);
  cudaGetSymbolAddress((void**)&Yb, g_Y);

  __nv_bfloat16 *qh, *ql, *kvh, *kvl, *yh, *yl, *wh, *wl;
  cudaGetSymbolAddress((void**)&qh, g_qh);
  cudaGetSymbolAddress((void**)&ql, g_ql);
  cudaGetSymbolAddress((void**)&kvh, g_kvh);
  cudaGetSymbolAddress((void**)&kvl, g_kvl);
  cudaGetSymbolAddress((void**)&yh, g_yh);
  cudaGetSymbolAddress((void**)&yl, g_yl);
  cudaGetSymbolAddress((void**)&wh, g_wh);
  cudaGetSymbolAddress((void**)&wl, g_wl);
  const size_t WSZ = (size_t)D_MODEL * D_MODEL;

  cudaFuncSetAttribute(flash_kernel,
                       cudaFuncAttributeMaxDynamicSharedMemorySize,
                       FLASH_SMEM_BYTES);
  cudaFuncSetAttribute(gemm_hmma_bf16x3,
                       cudaFuncAttributeMaxDynamicSharedMemorySize,
                       GSMEM_BYTES);

  const int NQ = BATCH * TQ * D_MODEL;    // 4M
  const int NKV = BATCH * SKV * D_MODEL;  // 8M
  const int NW = D_MODEL * D_MODEL;       // 1M

  // Split inputs/weights into bf16 hi/lo pairs.
  cvt_bf16x2_kernel<<<NQ / 1024, 256>>>(query, qh, ql, NQ);
  cvt_bf16x2_kernel<<<NKV / 1024, 256>>>(key_value, kvh, kvl, NKV);
  cvt_bf16x2_kernel<<<NW / 1024, 256>>>(Wq, wh + 0 * WSZ, wl + 0 * WSZ, NW);
  cvt_bf16x2_kernel<<<NW / 1024, 256>>>(Wk, wh + 1 * WSZ, wl + 1 * WSZ, NW);
  cvt_bf16x2_kernel<<<NW / 1024, 256>>>(Wv, wh + 2 * WSZ, wl + 2 * WSZ, NW);
  cvt_bf16x2_kernel<<<NW / 1024, 256>>>(Wo, wh + 3 * WSZ, wl + 3 * WSZ, NW);

  // Projections on HMMA (bf16x3).
  gemm_hmma_bf16x3<<<dim3(8, 32), 256, GSMEM_BYTES>>>(
      qh, ql, wh + 0 * WSZ, wl + 0 * WSZ, Qb, BATCH * TQ, D_MODEL, D_MODEL);
  gemm_hmma_bf16x3<<<dim3(8, 64), 256, GSMEM_BYTES>>>(
      kvh, kvl, wh + 1 * WSZ, wl + 1 * WSZ, Kb, BATCH * SKV, D_MODEL, D_MODEL);
  gemm_hmma_bf16x3<<<dim3(8, 64), 256, GSMEM_BYTES>>>(
      kvh, kvl, wh + 2 * WSZ, wl + 2 * WSZ, Vb, BATCH * SKV, D_MODEL, D_MODEL);

  // Attention (fp32 flash, smem-vectorized).
  flash_kernel<<<dim3(TQ / 64, NHEADS, BATCH), 256, FLASH_SMEM_BYTES>>>(
      Qb, Kb, Vb, imp, Yb);

  // Output projection.
  cvt_bf16x2_kernel<<<NQ / 1024, 256>>>(Yb, yh, yl, NQ);
  gemm_hmma_bf16x3<<<dim3(8, 32), 256, GSMEM_BYTES>>>(
      yh, yl, wh + 3 * WSZ, wl + 3 * WSZ, out, BATCH * TQ, D_MODEL, D_MODEL);
}

// round 5
// speedup vs baseline: 2.6979x; 2.2278x over previous
#include <cuda_runtime.h>
#include <cuda_bf16.h>
#include <cstdint>
#include <math.h>

#define D_MODEL 1024
#define BATCH   2
#define TQ      2048
#define SKV     4096
#define NHEADS  16
#define HDIM    64

// ---------------- scratch (no cudaMalloc allowed) ----------------
__device__ float g_Q[(size_t)BATCH * TQ  * D_MODEL];
__device__ float g_K[(size_t)BATCH * SKV * D_MODEL];
__device__ float g_V[(size_t)BATCH * SKV * D_MODEL];
__device__ float g_Y[(size_t)BATCH * TQ  * D_MODEL];

__device__ __nv_bfloat16 g_qh[(size_t)BATCH * TQ  * D_MODEL];
__device__ __nv_bfloat16 g_ql[(size_t)BATCH * TQ  * D_MODEL];
__device__ __nv_bfloat16 g_kvh[(size_t)BATCH * SKV * D_MODEL];
__device__ __nv_bfloat16 g_kvl[(size_t)BATCH * SKV * D_MODEL];
__device__ __nv_bfloat16 g_yh[(size_t)BATCH * TQ  * D_MODEL];
__device__ __nv_bfloat16 g_yl[(size_t)BATCH * TQ  * D_MODEL];
__device__ __nv_bfloat16 g_wh[4][(size_t)D_MODEL * D_MODEL];
__device__ __nv_bfloat16 g_wl[4][(size_t)D_MODEL * D_MODEL];

// bf16 hi/lo of K-proj (row-major) and V-proj (transposed per head: [b,h,d,S]).
__device__ __nv_bfloat16 g_kfh[(size_t)BATCH * SKV * D_MODEL];
__device__ __nv_bfloat16 g_kfl[(size_t)BATCH * SKV * D_MODEL];
__device__ __nv_bfloat16 g_vth[(size_t)BATCH * NHEADS * HDIM * SKV];
__device__ __nv_bfloat16 g_vtl[(size_t)BATCH * NHEADS * HDIM * SKV];

// ---------------- portable sm_80+ primitives ----------------
__device__ __forceinline__ uint32_t smem_u32(const void* p) {
  uint32_t a;
  asm("{ .reg .u64 t; cvta.to.shared.u64 t, %1; cvt.u32.u64 %0, t; }"
      : "=r"(a) : "l"(p));
  return a;
}
__device__ __forceinline__ void ldsm4(uint32_t* r, uint32_t a) {
  asm volatile("ldmatrix.sync.aligned.m8n8.x4.shared.b16 {%0,%1,%2,%3}, [%4];"
               : "=r"(r[0]), "=r"(r[1]), "=r"(r[2]), "=r"(r[3]) : "r"(a));
}
__device__ __forceinline__ void mma16816(float* d, const uint32_t* a,
                                         const uint32_t* b) {
  asm volatile(
      "mma.sync.aligned.m16n8k16.row.col.f32.bf16.bf16.f32 "
      "{%0,%1,%2,%3}, {%4,%5,%6,%7}, {%8,%9}, {%0,%1,%2,%3};"
      : "+f"(d[0]), "+f"(d[1]), "+f"(d[2]), "+f"(d[3])
      : "r"(a[0]), "r"(a[1]), "r"(a[2]), "r"(a[3]), "r"(b[0]), "r"(b[1]));
}
__device__ __forceinline__ void cp16(uint32_t dst, const void* src) {
  asm volatile("cp.async.cg.shared.global [%0], [%1], 16;" :: "r"(dst), "l"(src));
}
#define CP_COMMIT() asm volatile("cp.async.commit_group;")

__device__ __forceinline__ void pack_hilo(float p0, float p1, uint32_t& hi,
                                          uint32_t& lo) {
  __nv_bfloat162 h = __floats2bfloat162_rn(p0, p1);
  float r0 = p0 - __bfloat162float(h.x);
  float r1 = p1 - __bfloat162float(h.y);
  __nv_bfloat162 l = __floats2bfloat162_rn(r0, r1);
  hi = *reinterpret_cast<uint32_t*>(&h);
  lo = *reinterpret_cast<uint32_t*>(&l);
}

// ---------------------------------------------------------------------------
// f32 -> (bf16 hi, bf16 lo) split conversion. n multiple of 1024.
// ---------------------------------------------------------------------------
__global__ void cvt_bf16x2_kernel(const float* __restrict__ x,
                                  __nv_bfloat16* __restrict__ hi,
                                  __nv_bfloat16* __restrict__ lo, int n) {
  int i = (blockIdx.x * blockDim.x + threadIdx.x) * 4;
  if (i >= n) return;
  float4 v = *(const float4*)(x + i);
  uint32_t h0, l0, h1, l1;
  pack_hilo(v.x, v.y, h0, l0);
  pack_hilo(v.z, v.w, h1, l1);
  *(uint2*)(hi + i) = make_uint2(h0, h1);
  *(uint2*)(lo + i) = make_uint2(l0, l1);
}

// ---------------------------------------------------------------------------
// V transpose + bf16 hi/lo: V[b,s,h*64+d] -> vt[(b*16+h)*64+d][s].
// grid (SKV/64, NHEADS, BATCH), 256 threads.
// NOTE: shared row stride 65 floats is not 16B-aligned -> scalar stores only.
// ---------------------------------------------------------------------------
__global__ void vtrans_kernel(const float* __restrict__ V,
                              __nv_bfloat16* __restrict__ vth,
                              __nv_bfloat16* __restrict__ vtl) {
  __shared__ float t[64][65];
  const int b = blockIdx.z, h = blockIdx.y, s0 = blockIdx.x * 64;
  const int tid = threadIdx.x;
  const int ts = tid >> 2, c0 = (tid & 3) * 16;
#pragma unroll
  for (int i = 0; i < 4; i++) {
    float4 v = *(const float4*)(V + ((size_t)(b * SKV + s0 + ts)) * D_MODEL +
                                h * HDIM + c0 + i * 4);
    t[ts][c0 + i * 4 + 0] = v.x;   // scalar stores: row base not 16B-aligned
    t[ts][c0 + i * 4 + 1] = v.y;
    t[ts][c0 + i * 4 + 2] = v.z;
    t[ts][c0 + i * 4 + 3] = v.w;
  }
  __syncthreads();
  const int dr = tid >> 2, sc = (tid & 3) * 16;
  size_t rowbase = ((size_t)((b * NHEADS + h) * HDIM + dr)) * SKV + s0;
#pragma unroll
  for (int i = 0; i < 4; i++) {
    int s = sc + i * 4;
    uint32_t h0, l0, h1, l1;
    pack_hilo(t[s][dr], t[s + 1][dr], h0, l0);
    pack_hilo(t[s + 2][dr], t[s + 3][dr], h1, l1);
    *(uint2*)(vth + rowbase + s) = make_uint2(h0, h1);
    *(uint2*)(vtl + rowbase + s) = make_uint2(l0, l1);
  }
}

// ---------------------------------------------------------------------------
// bf16x3 NT GEMM on mma.sync (HMMA) — unchanged (proven in round 3).
// ---------------------------------------------------------------------------
#define GST 40
#define GTILE_HALFS (128 * GST)
#define GTILE_BYTES (GTILE_HALFS * 2)
#define GSTAGE_BYTES (4 * GTILE_BYTES)
#define GSMEM_BYTES (2 * GSTAGE_BYTES)

__global__ __launch_bounds__(256, 2)
void gemm_hmma_bf16x3(const __nv_bfloat16* __restrict__ Ah,
                      const __nv_bfloat16* __restrict__ Al,
                      const __nv_bfloat16* __restrict__ Bh,
                      const __nv_bfloat16* __restrict__ Bl,
                      float* __restrict__ C, int M, int N, int K) {
  extern __shared__ __align__(16) __nv_bfloat16 gsm[];
  const uint32_t sbase = smem_u32(gsm);
  const int tid = threadIdx.x, lane = tid & 31, warp = tid >> 5;
  const int wm = (warp & 3) * 32;
  const int wn = (warp >> 2) * 64;
  const int bm = blockIdx.y * 128;
  const int bn = blockIdx.x * 128;

  float acc[2][8][4];
#pragma unroll
  for (int mi = 0; mi < 2; mi++)
#pragma unroll
    for (int nj = 0; nj < 8; nj++)
#pragma unroll
      for (int q = 0; q < 4; q++) acc[mi][nj][q] = 0.0f;

#define LOAD_CHUNK(kc, stage) do {                                          \
    int kof_ = (kc) << 5;                                                   \
    _Pragma("unroll")                                                       \
    for (int j_ = 0; j_ < 2; j_++) {                                        \
      int idx_ = tid + j_ * 256;                                            \
      int r_ = idx_ >> 2, s_ = (idx_ & 3) * 8;                              \
      size_t ga_ = (size_t)(bm + r_) * K + kof_ + s_;                       \
      size_t gb_ = (size_t)(bn + r_) * K + kof_ + s_;                       \
      uint32_t d_ = sbase + (uint32_t)(stage) * GSTAGE_BYTES +              \
                    (uint32_t)(r_ * GST + s_) * 2;                          \
      cp16(d_,                   Ah + ga_);                                 \
      cp16(d_ + 1 * GTILE_BYTES, Al + ga_);                                 \
      cp16(d_ + 2 * GTILE_BYTES, Bh + gb_);                                 \
      cp16(d_ + 3 * GTILE_BYTES, Bl + gb_);                                 \
    }                                                                       \
  } while (0)

  const int nch = K >> 5;
  LOAD_CHUNK(0, 0);
  CP_COMMIT();

  const int ar = lane & 15;
  const int ac = ((lane >> 4) & 1) * 8;
  const int nof = ((lane >> 4) & 1) * 8 + (lane & 7);
  const int kof2 = ((lane >> 3) & 1) * 8;

  for (int c = 0; c < nch; c++) {
    const int cur = c & 1;
    if (c + 1 < nch) {
      LOAD_CHUNK(c + 1, cur ^ 1);
      CP_COMMIT();
      asm volatile("cp.async.wait_group 1;");
    } else {
      asm volatile("cp.async.wait_group 0;");
    }
    __syncthreads();

    const uint32_t st = sbase + (uint32_t)cur * GSTAGE_BYTES;
#pragma unroll
    for (int ks = 0; ks < 2; ks++) {
      const int k0 = ks * 16;
      uint32_t afh[2][4], afl[2][4];
#pragma unroll
      for (int mi = 0; mi < 2; mi++) {
        uint32_t ad = st + (uint32_t)((wm + mi * 16 + ar) * GST + k0 + ac) * 2;
        ldsm4(afh[mi], ad);
        ldsm4(afl[mi], ad + GTILE_BYTES);
      }
#pragma unroll
      for (int ni = 0; ni < 4; ni++) {
        uint32_t bd = st + 2 * GTILE_BYTES +
                      (uint32_t)((wn + ni * 16 + nof) * GST + k0 + kof2) * 2;
        uint32_t bh[4], bl[4];
        ldsm4(bh, bd);
        ldsm4(bl, bd + GTILE_BYTES);
#pragma unroll
        for (int mi = 0; mi < 2; mi++)
#pragma unroll
          for (int hhalf = 0; hhalf < 2; hhalf++) {
            int nj = ni * 2 + hhalf;
            mma16816(acc[mi][nj], afh[mi], &bh[2 * hhalf]);
            mma16816(acc[mi][nj], afh[mi], &bl[2 * hhalf]);
            mma16816(acc[mi][nj], afl[mi], &bh[2 * hhalf]);
          }
      }
    }
    __syncthreads();
  }

  const int crow = lane >> 2;
  const int ccol = (lane & 3) * 2;
#pragma unroll
  for (int mi = 0; mi < 2; mi++)
#pragma unroll
    for (int nj = 0; nj < 8; nj++) {
      int r0 = bm + wm + mi * 16 + crow;
      int cc = bn + wn + nj * 8 + ccol;
      *(float2*)(C + (size_t)r0 * N + cc) =
          make_float2(acc[mi][nj][0], acc[mi][nj][1]);
      *(float2*)(C + (size_t)(r0 + 8) * N + cc) =
          make_float2(acc[mi][nj][2], acc[mi][nj][3]);
    }
}

// ---------------------------------------------------------------------------
// HMMA flash attention, bf16x3 for QK^T and PV, P register-resident.
// BQ=128 (8 warps x m16), BS=64, d=64. cp.async double-buffered K/V stages.
// smem rows: 64 halves data, stride 72 halves (144B) -> 16B-aligned rows.
// Stage: Kh | Kl | Vh | Vl, 9216B each = 36864B; two stages = 73728B.
// Q (128x64 hi/lo) staged in stage-1 region, consumed to regs up front.
// ---------------------------------------------------------------------------
#define FROWB 144
#define FTILEB (64 * FROWB)          // 9216
#define FSTAGEB (4 * FTILEB)         // 36864
#define FQOFF FSTAGEB
#define FLASH2_SMEM (2 * FSTAGEB)    // 73728

__global__ __launch_bounds__(256)
void flash_hmma(const __nv_bfloat16* __restrict__ qfh,
                const __nv_bfloat16* __restrict__ qfl,
                const __nv_bfloat16* __restrict__ kfh,
                const __nv_bfloat16* __restrict__ kfl,
                const __nv_bfloat16* __restrict__ vth,
                const __nv_bfloat16* __restrict__ vtl,
                const float* __restrict__ imp, float* __restrict__ Y) {
  extern __shared__ __align__(16) char fsm[];
  const uint32_t sb = smem_u32(fsm);
  const int b = blockIdx.z, h = blockIdx.y, q0 = blockIdx.x * 128;
  const int tid = threadIdx.x, lane = tid & 31, warp = tid >> 5;
  const int wm = warp * 16;

  // ---- stage Q tile (128 x 64 halves, hi & lo) ----
  {
    const __nv_bfloat16* Qg = qfh + ((size_t)(b * TQ + q0)) * D_MODEL + h * HDIM;
    const __nv_bfloat16* Qg2 = qfl + ((size_t)(b * TQ + q0)) * D_MODEL + h * HDIM;
#pragma unroll
    for (int j = 0; j < 4; j++) {
      int idx = tid + j * 256;           // 0..1023
      int r = idx >> 3, c = (idx & 7) * 8;
      uint32_t d = sb + FQOFF + (uint32_t)(r * FROWB + c * 2);
      cp16(d, Qg + (size_t)r * D_MODEL + c);
      cp16(d + 128 * FROWB, Qg2 + (size_t)r * D_MODEL + c);
    }
  }
  CP_COMMIT();

  const __nv_bfloat16* Kgh = kfh + ((size_t)b * SKV) * D_MODEL + h * HDIM;
  const __nv_bfloat16* Kgl = kfl + ((size_t)b * SKV) * D_MODEL + h * HDIM;
  const __nv_bfloat16* Vgh = vth + ((size_t)((b * NHEADS + h) * HDIM)) * SKV;
  const __nv_bfloat16* Vgl = vtl + ((size_t)((b * NHEADS + h) * HDIM)) * SKV;

#define FLOAD_KV(s0_, stage_) do {                                            \
    uint32_t st_ = sb + (uint32_t)(stage_) * FSTAGEB;                         \
    _Pragma("unroll")                                                         \
    for (int j_ = 0; j_ < 2; j_++) {                                          \
      int idx_ = tid + j_ * 256;        /* 0..511 */                          \
      int r_ = idx_ >> 3, c_ = (idx_ & 7) * 8;                                \
      uint32_t d_ = st_ + (uint32_t)(r_ * FROWB + c_ * 2);                    \
      size_t gk_ = (size_t)((s0_) + r_) * D_MODEL + c_;                       \
      size_t gv_ = (size_t)r_ * SKV + (s0_) + c_;                             \
      cp16(d_,               Kgh + gk_);                                      \
      cp16(d_ + 1 * FTILEB,  Kgl + gk_);                                      \
      cp16(d_ + 2 * FTILEB,  Vgh + gv_);                                      \
      cp16(d_ + 3 * FTILEB,  Vgl + gv_);                                      \
    }                                                                         \
  } while (0)

  FLOAD_KV(0, 0);
  CP_COMMIT();

  // ---- consume Q into A-fragments ----
  const int ar = lane & 15;
  const int ac = ((lane >> 4) & 1) * 8;
  const int nof = ((lane >> 4) & 1) * 8 + (lane & 7);
  const int kof2 = ((lane >> 3) & 1) * 8;

  asm volatile("cp.async.wait_group 1;");
  __syncthreads();
  uint32_t qfa[4][4], qfb[4][4];
#pragma unroll
  for (int kc = 0; kc < 4; kc++) {
    uint32_t ad = sb + FQOFF + (uint32_t)((wm + ar) * FROWB + (kc * 16 + ac) * 2);
    ldsm4(qfa[kc], ad);
    ldsm4(qfb[kc], ad + 128 * FROWB);
  }
  __syncthreads();  // all warps done with Q region before stage-1 prefetch

  // ---- per-thread importance mask (cols mod 16) ----
  const int q2 = (lane & 3) * 2;
  float lg[4];
  lg[0] = logf(fmaxf(imp[b * NHEADS + (q2 & 15)], 1e-6f));
  lg[1] = logf(fmaxf(imp[b * NHEADS + ((q2 + 1) & 15)], 1e-6f));
  lg[2] = logf(fmaxf(imp[b * NHEADS + ((q2 + 8) & 15)], 1e-6f));
  lg[3] = logf(fmaxf(imp[b * NHEADS + ((q2 + 9) & 15)], 1e-6f));

  float m0 = -INFINITY, m1 = -INFINITY, l0 = 0.0f, l1 = 0.0f;
  float y[8][4];
#pragma unroll
  for (int nf = 0; nf < 8; nf++)
#pragma unroll
    for (int q = 0; q < 4; q++) y[nf][q] = 0.0f;

  const int NT = SKV / 64;
  for (int t = 0; t < NT; t++) {
    const int cur = t & 1;
    if (t + 1 < NT) {
      FLOAD_KV((t + 1) * 64, cur ^ 1);
      CP_COMMIT();
      asm volatile("cp.async.wait_group 1;");
    } else {
      asm volatile("cp.async.wait_group 0;");
    }
    __syncthreads();
    const uint32_t st = sb + (uint32_t)cur * FSTAGEB;

    // ---- S = Q K^T (bf16x3) ----
    float s[8][4];
#pragma unroll
    for (int nf = 0; nf < 8; nf++)
#pragma unroll
      for (int q = 0; q < 4; q++) s[nf][q] = 0.0f;
#pragma unroll
    for (int kc = 0; kc < 4; kc++) {
#pragma unroll
      for (int n2 = 0; n2 < 4; n2++) {
        uint32_t bd = st + (uint32_t)((n2 * 16 + nof) * FROWB + (kc * 16 + kof2) * 2);
        uint32_t bh[4], bl[4];
        ldsm4(bh, bd);
        ldsm4(bl, bd + FTILEB);
#pragma unroll
        for (int hh = 0; hh < 2; hh++) {
          mma16816(s[n2 * 2 + hh], qfa[kc], &bh[2 * hh]);
          mma16816(s[n2 * 2 + hh], qfa[kc], &bl[2 * hh]);
          mma16816(s[n2 * 2 + hh], qfb[kc], &bh[2 * hh]);
        }
      }
    }

    // ---- scale + mask + online softmax ----
    float mt0 = -INFINITY, mt1 = -INFINITY;
#pragma unroll
    for (int nf = 0; nf < 8; nf++) {
      const int p = (nf & 1) * 2;
      s[nf][0] = s[nf][0] * 0.125f + lg[p];
      s[nf][1] = s[nf][1] * 0.125f + lg[p + 1];
      s[nf][2] = s[nf][2] * 0.125f + lg[p];
      s[nf][3] = s[nf][3] * 0.125f + lg[p + 1];
      mt0 = fmaxf(mt0, fmaxf(s[nf][0], s[nf][1]));
      mt1 = fmaxf(mt1, fmaxf(s[nf][2], s[nf][3]));
    }
    mt0 = fmaxf(mt0, __shfl_xor_sync(0xffffffffu, mt0, 1));
    mt0 = fmaxf(mt0, __shfl_xor_sync(0xffffffffu, mt0, 2));
    mt1 = fmaxf(mt1, __shfl_xor_sync(0xffffffffu, mt1, 1));
    mt1 = fmaxf(mt1, __shfl_xor_sync(0xffffffffu, mt1, 2));

    float mn0 = fmaxf(m0, mt0), mn1 = fmaxf(m1, mt1);
    float c0 = __expf(m0 - mn0), c1 = __expf(m1 - mn1);
    m0 = mn0; m1 = mn1;

    uint32_t ph[4][4], pl[4][4];
    float r0 = 0.0f, r1 = 0.0f;
#pragma unroll
    for (int nf = 0; nf < 8; nf++) {
      float p0 = __expf(s[nf][0] - m0);
      float p1 = __expf(s[nf][1] - m0);
      float p2 = __expf(s[nf][2] - m1);
      float p3 = __expf(s[nf][3] - m1);
      r0 += p0 + p1;
      r1 += p2 + p3;
      const int kc = nf >> 1, o = (nf & 1) * 2;
      pack_hilo(p0, p1, ph[kc][o], pl[kc][o]);
      pack_hilo(p2, p3, ph[kc][o + 1], pl[kc][o + 1]);
    }
    r0 += __shfl_xor_sync(0xffffffffu, r0, 1);
    r0 += __shfl_xor_sync(0xffffffffu, r0, 2);
    r1 += __shfl_xor_sync(0xffffffffu, r1, 1);
    r1 += __shfl_xor_sync(0xffffffffu, r1, 2);
    l0 = l0 * c0 + r0;
    l1 = l1 * c1 + r1;
#pragma unroll
    for (int nf = 0; nf < 8; nf++) {
      y[nf][0] *= c0; y[nf][1] *= c0;
      y[nf][2] *= c1; y[nf][3] *= c1;
    }

    // ---- y += P V (bf16x3) ----
#pragma unroll
    for (int kc = 0; kc < 4; kc++) {
#pragma unroll
      for (int n2 = 0; n2 < 4; n2++) {
        uint32_t bd = st + 2 * FTILEB +
                      (uint32_t)((n2 * 16 + nof) * FROWB + (kc * 16 + kof2) * 2);
        uint32_t vh[4], vl[4];
        ldsm4(vh, bd);
        ldsm4(vl, bd + FTILEB);
#pragma unroll
        for (int hh = 0; hh < 2; hh++) {
          mma16816(y[n2 * 2 + hh], ph[kc], &vh[2 * hh]);
          mma16816(y[n2 * 2 + hh], ph[kc], &vl[2 * hh]);
          mma16816(y[n2 * 2 + hh], pl[kc], &vh[2 * hh]);
        }
      }
    }
    __syncthreads();  // stage reuse safety before next prefetch
  }

  // ---- epilogue ----
  const float i0 = 1.0f / l0, i1 = 1.0f / l1;
  const int row0 = q0 + wm + (lane >> 2);
#pragma unroll
  for (int nf = 0; nf < 8; nf++) {
    int d0 = 8 * nf + q2;
    *(float2*)(Y + ((size_t)b * TQ + row0) * D_MODEL + h * HDIM + d0) =
        make_float2(y[nf][0] * i0, y[nf][1] * i0);
    *(float2*)(Y + ((size_t)b * TQ + row0 + 8) * D_MODEL + h * HDIM + d0) =
        make_float2(y[nf][2] * i1, y[nf][3] * i1);
  }
}

// ---------------------------------------------------------------------------
extern "C" void kernel_launch(void* const* d_in, const int* in_sizes, int n_in,
                              void* d_out, int out_size) {
  const float* query     = (const float*)d_in[0];
  const float* key_value = (const float*)d_in[1];
  const float* imp       = (const float*)d_in[2];
  const float* Wq        = (const float*)d_in[3];
  const float* Wk        = (const float*)d_in[4];
  const float* Wv        = (const float*)d_in[5];
  const float* Wo        = (const float*)d_in[6];
  float* out = (float*)d_out;

  float *Qb, *Kb, *Vb, *Yb;
  cudaGetSymbolAddress((void**)&Qb, g_Q);
  cudaGetSymbolAddress((void**)&Kb, g_K);
  cudaGetSymbolAddress((void**)&Vb, g_V);
  cudaGetSymbolAddress((void**)&Yb, g_Y);

  __nv_bfloat16 *qh, *ql, *kvh, *kvl, *yh, *yl, *wh, *wl, *kfh, *kfl, *vth, *vtl;
  cudaGetSymbolAddress((void**)&qh, g_qh);
  cudaGetSymbolAddress((void**)&ql, g_ql);
  cudaGetSymbolAddress((void**)&kvh, g_kvh);
  cudaGetSymbolAddress((void**)&kvl, g_kvl);
  cudaGetSymbolAddress((void**)&yh, g_yh);
  cudaGetSymbolAddress((void**)&yl, g_yl);
  cudaGetSymbolAddress((void**)&wh, g_wh);
  cudaGetSymbolAddress((void**)&wl, g_wl);
  cudaGetSymbolAddress((void**)&kfh, g_kfh);
  cudaGetSymbolAddress((void**)&kfl, g_kfl);
  cudaGetSymbolAddress((void**)&vth, g_vth);
  cudaGetSymbolAddress((void**)&vtl, g_vtl);
  const size_t WSZ = (size_t)D_MODEL * D_MODEL;

  cudaFuncSetAttribute(gemm_hmma_bf16x3,
                       cudaFuncAttributeMaxDynamicSharedMemorySize, GSMEM_BYTES);
  cudaFuncSetAttribute(flash_hmma,
                       cudaFuncAttributeMaxDynamicSharedMemorySize, FLASH2_SMEM);

  const int NQ = BATCH * TQ * D_MODEL;
  const int NKV = BATCH * SKV * D_MODEL;
  const int NW = D_MODEL * D_MODEL;

  // Split raw inputs/weights into bf16 hi/lo pairs.
  cvt_bf16x2_kernel<<<NQ / 1024, 256>>>(query, qh, ql, NQ);
  cvt_bf16x2_kernel<<<NKV / 1024, 256>>>(key_value, kvh, kvl, NKV);
  cvt_bf16x2_kernel<<<NW / 1024, 256>>>(Wq, wh + 0 * WSZ, wl + 0 * WSZ, NW);
  cvt_bf16x2_kernel<<<NW / 1024, 256>>>(Wk, wh + 1 * WSZ, wl + 1 * WSZ, NW);
  cvt_bf16x2_kernel<<<NW / 1024, 256>>>(Wv, wh + 2 * WSZ, wl + 2 * WSZ, NW);
  cvt_bf16x2_kernel<<<NW / 1024, 256>>>(Wo, wh + 3 * WSZ, wl + 3 * WSZ, NW);

  // Projections (HMMA bf16x3).
  gemm_hmma_bf16x3<<<dim3(8, 32), 256, GSMEM_BYTES>>>(
      qh, ql, wh + 0 * WSZ, wl + 0 * WSZ, Qb, BATCH * TQ, D_MODEL, D_MODEL);
  gemm_hmma_bf16x3<<<dim3(8, 64), 256, GSMEM_BYTES>>>(
      kvh, kvl, wh + 1 * WSZ, wl + 1 * WSZ, Kb, BATCH * SKV, D_MODEL, D_MODEL);
  gemm_hmma_bf16x3<<<dim3(8, 64), 256, GSMEM_BYTES>>>(
      kvh, kvl, wh + 2 * WSZ, wl + 2 * WSZ, Vb, BATCH * SKV, D_MODEL, D_MODEL);

  // Convert projections for HMMA flash (qh/ql reused for projected Q).
  cvt_bf16x2_kernel<<<NQ / 1024, 256>>>(Qb, qh, ql, NQ);
  cvt_bf16x2_kernel<<<NKV / 1024, 256>>>(Kb, kfh, kfl, NKV);
  vtrans_kernel<<<dim3(SKV / 64, NHEADS, BATCH), 256>>>(Vb, vth, vtl);

  // HMMA flash attention.
  flash_hmma<<<dim3(TQ / 128, NHEADS, BATCH), 256, FLASH2_SMEM>>>(
      qh, ql, kfh, kfl, vth, vtl, imp, Yb);

  // Output projection.
  cvt_bf16x2_kernel<<<NQ / 1024, 256>>>(Yb, yh, yl, NQ);
  gemm_hmma_bf16x3<<<dim3(8, 32), 256, GSMEM_BYTES>>>(
      yh, yl, wh + 3 * WSZ, wl + 3 * WSZ, out, BATCH * TQ, D_MODEL, D_MODEL);
}

// round 6
// speedup vs baseline: 3.3252x; 1.2325x over previous
#include <cuda_runtime.h>
#include <cuda_bf16.h>
#include <cstdint>
#include <math.h>

#define D_MODEL 1024
#define BATCH   2
#define TQ      2048
#define SKV     4096
#define NHEADS  16
#define HDIM    64

// ---------------- scratch (no cudaMalloc allowed) ----------------
__device__ float g_Q[(size_t)BATCH * TQ  * D_MODEL];
__device__ float g_K[(size_t)BATCH * SKV * D_MODEL];
__device__ float g_V[(size_t)BATCH * SKV * D_MODEL];
__device__ float g_Y[(size_t)BATCH * TQ  * D_MODEL];

// GEMM A-operand packed tiles (also reused as flash-Q pack after Q-GEMM).
__device__ __align__(256) __nv_bfloat16 g_qh[(size_t)BATCH * TQ  * D_MODEL];
__device__ __align__(256) __nv_bfloat16 g_ql[(size_t)BATCH * TQ  * D_MODEL];
__device__ __align__(256) __nv_bfloat16 g_kvh[(size_t)BATCH * SKV * D_MODEL];
__device__ __align__(256) __nv_bfloat16 g_kvl[(size_t)BATCH * SKV * D_MODEL];
__device__ __align__(256) __nv_bfloat16 g_yh[(size_t)BATCH * TQ  * D_MODEL];
__device__ __align__(256) __nv_bfloat16 g_yl[(size_t)BATCH * TQ  * D_MODEL];
__device__ __align__(256) __nv_bfloat16 g_wh[4][(size_t)D_MODEL * D_MODEL];
__device__ __align__(256) __nv_bfloat16 g_wl[4][(size_t)D_MODEL * D_MODEL];
// flash packed K tiles and transposed V tiles.
__device__ __align__(256) __nv_bfloat16 g_kfh[(size_t)BATCH * SKV * D_MODEL];
__device__ __align__(256) __nv_bfloat16 g_kfl[(size_t)BATCH * SKV * D_MODEL];
__device__ __align__(256) __nv_bfloat16 g_vth[(size_t)BATCH * NHEADS * HDIM * SKV];
__device__ __align__(256) __nv_bfloat16 g_vtl[(size_t)BATCH * NHEADS * HDIM * SKV];

// ---------------- primitives ----------------
__device__ __forceinline__ uint32_t smem_u32(const void* p) {
  uint32_t a;
  asm("{ .reg .u64 t; cvta.to.shared.u64 t, %1; cvt.u32.u64 %0, t; }"
      : "=r"(a) : "l"(p));
  return a;
}
__device__ __forceinline__ void ldsm4(uint32_t* r, uint32_t a) {
  asm volatile("ldmatrix.sync.aligned.m8n8.x4.shared.b16 {%0,%1,%2,%3}, [%4];"
               : "=r"(r[0]), "=r"(r[1]), "=r"(r[2]), "=r"(r[3]) : "r"(a));
}
__device__ __forceinline__ void mma16816(float* d, const uint32_t* a,
                                         const uint32_t* b) {
  asm volatile(
      "mma.sync.aligned.m16n8k16.row.col.f32.bf16.bf16.f32 "
      "{%0,%1,%2,%3}, {%4,%5,%6,%7}, {%8,%9}, {%0,%1,%2,%3};"
      : "+f"(d[0]), "+f"(d[1]), "+f"(d[2]), "+f"(d[3])
      : "r"(a[0]), "r"(a[1]), "r"(a[2]), "r"(a[3]), "r"(b[0]), "r"(b[1]));
}
__device__ __forceinline__ void cp16(uint32_t dst, const void* src) {
  asm volatile("cp.async.cg.shared.global [%0], [%1], 16;" :: "r"(dst), "l"(src));
}
#define CP_COMMIT() asm volatile("cp.async.commit_group;")

// Bulk DMA: global -> shared, mbarrier completion (sm_90 PTX; UBLKCP in SASS).
__device__ __forceinline__ void bulk_g2s(uint32_t dst, const void* src,
                                         uint32_t bytes, uint32_t mbar) {
  asm volatile(
      "cp.async.bulk.shared::cluster.global.mbarrier::complete_tx::bytes "
      "[%0], [%1], %2, [%3];"
      :: "r"(dst), "l"(src), "r"(bytes), "r"(mbar) : "memory");
}
#define MBARRIER_INIT(mbar, count)                                            \
  asm volatile("mbarrier.init.shared.b64 [%0], %1;"                           \
               :: "r"((uint32_t)(mbar)), "r"((uint32_t)(count)) : "memory")
#define MBARRIER_EXPECT_TX(mbar, tx)                                          \
  asm volatile("mbarrier.arrive.expect_tx.shared.b64 _, [%0], %1;"            \
               :: "r"((uint32_t)(mbar)), "r"((uint32_t)(tx)) : "memory")
#define MBARRIER_WAIT_PARITY(mbar_addr, phase_parity) do {                    \
  uint32_t _mbar = (uint32_t)(mbar_addr);                                     \
  uint32_t _par = (uint32_t)(phase_parity);                                   \
  uint32_t _done;                                                             \
  asm volatile(                                                               \
      "{\n\t.reg .pred p;\n\t"                                                \
      "mbarrier.try_wait.parity.acquire.cta.shared::cta.b64 p, [%1], %2;\n\t" \
      "selp.b32 %0, 1, 0, p;\n\t}"                                            \
      : "=r"(_done) : "r"(_mbar), "r"(_par) : "memory");                      \
  if (!_done) {                                                               \
    asm volatile(                                                             \
        "{\n\t.reg .pred P1;\n\t"                                             \
        "WAIT_LOOP_%=:\n\t"                                                   \
        "mbarrier.try_wait.parity.acquire.cta.shared::cta.b64 P1, [%0], %1, 0x989680;\n\t" \
        "@P1 bra.uni WAIT_DONE_%=;\n\t"                                       \
        "bra.uni WAIT_LOOP_%=;\n\t"                                           \
        "WAIT_DONE_%=:\n\t}"                                                  \
        :: "r"(_mbar), "r"(_par) : "memory");                                 \
  }                                                                           \
} while (0)

__device__ __forceinline__ void pack_hilo(float p0, float p1, uint32_t& hi,
                                          uint32_t& lo) {
  __nv_bfloat162 h = __floats2bfloat162_rn(p0, p1);
  float r0 = p0 - __bfloat162float(h.x);
  float r1 = p1 - __bfloat162float(h.y);
  __nv_bfloat162 l = __floats2bfloat162_rn(r0, r1);
  hi = *reinterpret_cast<uint32_t*>(&h);
  lo = *reinterpret_cast<uint32_t*>(&l);
}

// ---------------------------------------------------------------------------
// fp32 [M,1024] row-major -> packed GEMM tiles [mb][kc 0..31][128x32 halves],
// 64B rows, seg swizzle seg^=((r>>1)&3). Emits bf16 hi/lo. n mult of 2048.
// ---------------------------------------------------------------------------
__global__ void cvt_pack_gemm(const float* __restrict__ x,
                              __nv_bfloat16* __restrict__ ph,
                              __nv_bfloat16* __restrict__ pl, int n) {
  int i = blockIdx.x * blockDim.x + threadIdx.x;
  if (i * 8 >= n) return;
  const float* src = x + (size_t)i * 8;
  float4 a = *(const float4*)src;
  float4 b = *(const float4*)(src + 4);
  uint32_t h0, h1, h2, h3, l0, l1, l2, l3;
  pack_hilo(a.x, a.y, h0, l0);
  pack_hilo(a.z, a.w, h1, l1);
  pack_hilo(b.x, b.y, h2, l2);
  pack_hilo(b.z, b.w, h3, l3);
  int m = (i * 8) >> 10, k = (i * 8) & 1023;
  int r = m & 127, mb = m >> 7, kc = k >> 5, seg = (k >> 3) & 3;
  size_t t = ((size_t)mb * 32 + kc) * 4096 + r * 32 +
             ((seg ^ ((r >> 1) & 3)) << 3);
  *(uint4*)(ph + t) = make_uint4(h0, h1, h2, h3);
  *(uint4*)(pl + t) = make_uint4(l0, l1, l2, l3);
}

// ---------------------------------------------------------------------------
// K-proj fp32 -> flash K tiles [b][h][t 0..63][64 keys x 64 halves], 128B
// rows, seg swizzle seg^=(r&7).
// ---------------------------------------------------------------------------
__global__ void kpack_flash(const float* __restrict__ K,
                            __nv_bfloat16* __restrict__ kh,
                            __nv_bfloat16* __restrict__ kl) {
  int idx = blockIdx.x * blockDim.x + threadIdx.x;   // BATCH*SKV*128 total
  int h8 = idx & 127;
  int h = h8 >> 3, d = (h8 & 7) * 8;
  int sg = idx >> 7;
  int b = sg >> 12, s = sg & 4095;
  const float* src = K + ((size_t)(b * SKV + s)) * D_MODEL + h * 64 + d;
  float4 a = *(const float4*)src;
  float4 c = *(const float4*)(src + 4);
  uint32_t h0, h1, h2, h3, l0, l1, l2, l3;
  pack_hilo(a.x, a.y, h0, l0);
  pack_hilo(a.z, a.w, h1, l1);
  pack_hilo(c.x, c.y, h2, l2);
  pack_hilo(c.z, c.w, h3, l3);
  int r = s & 63;
  size_t t = ((size_t)(b * 16 + h) * 64 + (s >> 6)) * 4096 + r * 64 +
             ((((d >> 3)) ^ (r & 7)) << 3);
  *(uint4*)(kh + t) = make_uint4(h0, h1, h2, h3);
  *(uint4*)(kl + t) = make_uint4(l0, l1, l2, l3);
}

// ---------------------------------------------------------------------------
// Q-proj fp32 -> flash Q tiles [b][h][qb 0..15][128 rows x 64 halves], 128B
// rows, seg swizzle seg^=(r&7).
// ---------------------------------------------------------------------------
__global__ void qpack_flash(const float* __restrict__ Q,
                            __nv_bfloat16* __restrict__ qh,
                            __nv_bfloat16* __restrict__ ql) {
  int idx = blockIdx.x * blockDim.x + threadIdx.x;   // BATCH*TQ*128 total
  int h8 = idx & 127;
  int h = h8 >> 3, d = (h8 & 7) * 8;
  int qg = idx >> 7;
  int b = qg >> 11, q = qg & 2047;
  const float* src = Q + ((size_t)(b * TQ + q)) * D_MODEL + h * 64 + d;
  float4 a = *(const float4*)src;
  float4 c = *(const float4*)(src + 4);
  uint32_t h0, h1, h2, h3, l0, l1, l2, l3;
  pack_hilo(a.x, a.y, h0, l0);
  pack_hilo(a.z, a.w, h1, l1);
  pack_hilo(c.x, c.y, h2, l2);
  pack_hilo(c.z, c.w, h3, l3);
  int r = q & 127;
  size_t t = ((size_t)(b * 16 + h) * 16 + (q >> 7)) * 8192 + r * 64 +
             ((((d >> 3)) ^ (r & 7)) << 3);
  *(uint4*)(qh + t) = make_uint4(h0, h1, h2, h3);
  *(uint4*)(ql + t) = make_uint4(l0, l1, l2, l3);
}

// ---------------------------------------------------------------------------
// V-proj fp32 -> transposed flash V tiles [b][h][t][64 d-rows x 64 s-halves],
// 128B rows, seg swizzle seg^=(d&7). grid (64, 16, 2), 256 thr.
// ---------------------------------------------------------------------------
__global__ void vpack_flash(const float* __restrict__ V,
                            __nv_bfloat16* __restrict__ vh,
                            __nv_bfloat16* __restrict__ vl) {
  __shared__ float t[64][65];
  const int b = blockIdx.z, h = blockIdx.y, s0 = blockIdx.x * 64;
  const int tid = threadIdx.x;
  const int ts = tid >> 2, c0 = (tid & 3) * 16;
#pragma unroll
  for (int i = 0; i < 4; i++) {
    float4 v = *(const float4*)(V + ((size_t)(b * SKV + s0 + ts)) * D_MODEL +
                                h * HDIM + c0 + i * 4);
    t[ts][c0 + i * 4 + 0] = v.x;
    t[ts][c0 + i * 4 + 1] = v.y;
    t[ts][c0 + i * 4 + 2] = v.z;
    t[ts][c0 + i * 4 + 3] = v.w;
  }
  __syncthreads();
#pragma unroll
  for (int it = 0; it < 2; it++) {
    int item = tid + it * 256;         // 0..511
    int d = item >> 3, cs = (item & 7) * 8;
    uint32_t h0, h1, h2, h3, l0, l1, l2, l3;
    pack_hilo(t[cs + 0][d], t[cs + 1][d], h0, l0);
    pack_hilo(t[cs + 2][d], t[cs + 3][d], h1, l1);
    pack_hilo(t[cs + 4][d], t[cs + 5][d], h2, l2);
    pack_hilo(t[cs + 6][d], t[cs + 7][d], h3, l3);
    size_t tb = ((size_t)(b * 16 + h) * 64 + blockIdx.x) * 4096 + d * 64 +
                ((((cs >> 3)) ^ (d & 7)) << 3);
    *(uint4*)(vh + tb) = make_uint4(h0, h1, h2, h3);
    *(uint4*)(vl + tb) = make_uint4(l0, l1, l2, l3);
  }
}

// ---------------------------------------------------------------------------
// bf16x3 NT GEMM on HMMA with bulk-DMA operand tiles.
// Block tile 128x128, BK=32, 8 warps (4m x 2n) each m32 x n64.
// smem: stage = Ah|Al|Bh|Bl 8KB tiles = 32KB; 2 stages + 2 mbars.
// ---------------------------------------------------------------------------
#define GS_TILE  8192
#define GS_STAGE 32768
#define GS_MBAR  65536
#define GS_SMEM  65664

__global__ __launch_bounds__(256, 2)
void gemm_bulk(const __nv_bfloat16* __restrict__ Ah,
               const __nv_bfloat16* __restrict__ Al,
               const __nv_bfloat16* __restrict__ Bh,
               const __nv_bfloat16* __restrict__ Bl,
               float* __restrict__ C, int M, int N, int K) {
  extern __shared__ __align__(128) char sm[];
  const uint32_t sb = smem_u32(sm);
  const int tid = threadIdx.x, lane = tid & 31, warp = tid >> 5;
  const int wm = (warp & 3) * 32;
  const int wn = (warp >> 2) * 64;
  const int bm = blockIdx.y * 128;
  const int bn = blockIdx.x * 128;
  const int nch = K >> 5;
  const int mb = bm >> 7, nb = bn >> 7;

  float acc[2][8][4];
#pragma unroll
  for (int mi = 0; mi < 2; mi++)
#pragma unroll
    for (int nj = 0; nj < 8; nj++)
#pragma unroll
      for (int q = 0; q < 4; q++) acc[mi][nj][q] = 0.0f;

  if (tid == 0) {
    MBARRIER_INIT(sb + GS_MBAR, 1);
    MBARRIER_INIT(sb + GS_MBAR + 8, 1);
  }
  __syncthreads();

#define G_PREFETCH(c_, s_) do {                                               \
    if (tid == 0) {                                                           \
      uint32_t mb_ = sb + GS_MBAR + (s_) * 8;                                 \
      MBARRIER_EXPECT_TX(mb_, 32768u);                                        \
      uint32_t d_ = sb + (uint32_t)(s_) * GS_STAGE;                           \
      const __nv_bfloat16* a_ = Ah + ((size_t)(mb * nch + (c_))) * 4096;      \
      const __nv_bfloat16* a2_ = Al + ((size_t)(mb * nch + (c_))) * 4096;     \
      const __nv_bfloat16* b_ = Bh + ((size_t)(nb * nch + (c_))) * 4096;      \
      const __nv_bfloat16* b2_ = Bl + ((size_t)(nb * nch + (c_))) * 4096;     \
      bulk_g2s(d_,              a_,  8192u, mb_);                             \
      bulk_g2s(d_ + GS_TILE,    a2_, 8192u, mb_);                             \
      bulk_g2s(d_ + 2*GS_TILE,  b_,  8192u, mb_);                             \
      bulk_g2s(d_ + 3*GS_TILE,  b2_, 8192u, mb_);                             \
    }                                                                         \
  } while (0)

  G_PREFETCH(0, 0);

  const int ar = lane & 15;
  const int ac = ((lane >> 4) & 1) * 8;
  const int nof = ((lane >> 4) & 1) * 8 + (lane & 7);
  const int kof2 = ((lane >> 3) & 1) * 8;

  for (int c = 0; c < nch; c++) {
    const int cur = c & 1;
    if (c + 1 < nch) G_PREFETCH(c + 1, cur ^ 1);
    MBARRIER_WAIT_PARITY(sb + GS_MBAR + cur * 8, (c >> 1) & 1);

    const uint32_t st = sb + (uint32_t)cur * GS_STAGE;
#pragma unroll
    for (int ks = 0; ks < 2; ks++) {
      const int k0 = ks * 16;
      uint32_t afh[2][4], afl[2][4];
#pragma unroll
      for (int mi = 0; mi < 2; mi++) {
        int r = wm + mi * 16 + ar;
        int seg = (k0 + ac) >> 3;
        uint32_t ad = st + (uint32_t)(r * 64 + ((seg ^ ((r >> 1) & 3)) << 4));
        ldsm4(afh[mi], ad);
        ldsm4(afl[mi], ad + GS_TILE);
      }
#pragma unroll
      for (int ni = 0; ni < 4; ni++) {
        int rb = wn + ni * 16 + nof;
        int segb = (k0 + kof2) >> 3;
        uint32_t bd = st + 2 * GS_TILE +
                      (uint32_t)(rb * 64 + ((segb ^ ((rb >> 1) & 3)) << 4));
        uint32_t bh[4], bl[4];
        ldsm4(bh, bd);
        ldsm4(bl, bd + GS_TILE);
#pragma unroll
        for (int mi = 0; mi < 2; mi++)
#pragma unroll
          for (int hh = 0; hh < 2; hh++) {
            int nj = ni * 2 + hh;
            mma16816(acc[mi][nj], afh[mi], &bh[2 * hh]);
            mma16816(acc[mi][nj], afh[mi], &bl[2 * hh]);
            mma16816(acc[mi][nj], afl[mi], &bh[2 * hh]);
          }
      }
    }
    __syncthreads();   // all warps done with stage cur before it is refilled
  }

  const int crow = lane >> 2;
  const int ccol = (lane & 3) * 2;
#pragma unroll
  for (int mi = 0; mi < 2; mi++)
#pragma unroll
    for (int nj = 0; nj < 8; nj++) {
      int r0 = bm + wm + mi * 16 + crow;
      int cc = bn + wn + nj * 8 + ccol;
      *(float2*)(C + (size_t)r0 * N + cc) =
          make_float2(acc[mi][nj][0], acc[mi][nj][1]);
      *(float2*)(C + (size_t)(r0 + 8) * N + cc) =
          make_float2(acc[mi][nj][2], acc[mi][nj][3]);
    }
}

// ---------------------------------------------------------------------------
// HMMA flash attention with bulk-DMA K/V tiles. BQ=128 (8 warps x m16),
// BS=64, d=64, bf16x3 QK^T and PV, P register-resident.
// smem: 2 stages (Kh|Kl|Vh|Vl 8KB each = 32KB) + Q 32KB + 2 mbars.
// ---------------------------------------------------------------------------
#define FS_TILE  8192
#define FS_STAGE 32768
#define FS_QOFF  65536
#define FS_MBAR  98304
#define FS_SMEM  98432

__global__ __launch_bounds__(256)
void flash_bulk(const __nv_bfloat16* __restrict__ qfh,
                const __nv_bfloat16* __restrict__ qfl,
                const __nv_bfloat16* __restrict__ kfh,
                const __nv_bfloat16* __restrict__ kfl,
                const __nv_bfloat16* __restrict__ vth,
                const __nv_bfloat16* __restrict__ vtl,
                const float* __restrict__ imp, float* __restrict__ Y) {
  extern __shared__ __align__(128) char fsm[];
  const uint32_t sb = smem_u32(fsm);
  const int b = blockIdx.z, h = blockIdx.y, qb = blockIdx.x;
  const int q0 = qb * 128;
  const int tid = threadIdx.x, lane = tid & 31, warp = tid >> 5;
  const int wm = warp * 16;

  if (tid == 0) {
    MBARRIER_INIT(sb + FS_MBAR, 1);
    MBARRIER_INIT(sb + FS_MBAR + 8, 1);
  }
  // Stage Q (two contiguous 16KB packed tiles) via cp.async.
  {
    const __nv_bfloat16* qsrc = qfh + ((size_t)(b * 16 + h) * 16 + qb) * 8192;
    const __nv_bfloat16* qsrc2 = qfl + ((size_t)(b * 16 + h) * 16 + qb) * 8192;
#pragma unroll
    for (int j = 0; j < 4; j++) {
      int idx = tid + j * 256;   // 0..1023 x16B = 16KB
      cp16(sb + FS_QOFF + idx * 16, qsrc + idx * 8);
      cp16(sb + FS_QOFF + 16384 + idx * 16, qsrc2 + idx * 8);
    }
  }
  CP_COMMIT();
  __syncthreads();               // mbar init visible to all

  const __nv_bfloat16* Kb = kfh + ((size_t)(b * 16 + h) * 64) * 4096;
  const __nv_bfloat16* Kb2 = kfl + ((size_t)(b * 16 + h) * 64) * 4096;
  const __nv_bfloat16* Vb = vth + ((size_t)(b * 16 + h) * 64) * 4096;
  const __nv_bfloat16* Vb2 = vtl + ((size_t)(b * 16 + h) * 64) * 4096;

#define F_PREFETCH(t_, s_) do {                                               \
    if (tid == 0) {                                                           \
      uint32_t mb_ = sb + FS_MBAR + (s_) * 8;                                 \
      MBARRIER_EXPECT_TX(mb_, 32768u);                                        \
      uint32_t d_ = sb + (uint32_t)(s_) * FS_STAGE;                           \
      bulk_g2s(d_,             Kb  + (size_t)(t_) * 4096, 8192u, mb_);        \
      bulk_g2s(d_ + FS_TILE,   Kb2 + (size_t)(t_) * 4096, 8192u, mb_);        \
      bulk_g2s(d_ + 2*FS_TILE, Vb  + (size_t)(t_) * 4096, 8192u, mb_);        \
      bulk_g2s(d_ + 3*FS_TILE, Vb2 + (size_t)(t_) * 4096, 8192u, mb_);        \
    }                                                                         \
  } while (0)

  F_PREFETCH(0, 0);

  const int ar = lane & 15;
  const int ac = ((lane >> 4) & 1) * 8;
  const int nof = ((lane >> 4) & 1) * 8 + (lane & 7);
  const int kof2 = ((lane >> 3) & 1) * 8;

  // Consume Q into A-fragments.
  asm volatile("cp.async.wait_group 0;");
  __syncthreads();
  uint32_t qfa[4][4], qfb[4][4];
#pragma unroll
  for (int kc = 0; kc < 4; kc++) {
    int r = wm + ar;
    int seg = 2 * kc + (ac >> 3);
    uint32_t ad = sb + FS_QOFF + (uint32_t)(r * 128 + ((seg ^ (r & 7)) << 4));
    ldsm4(qfa[kc], ad);
    ldsm4(qfb[kc], ad + 16384);
  }

  const int q2 = (lane & 3) * 2;
  float lg[4];
  lg[0] = logf(fmaxf(imp[b * NHEADS + (q2 & 15)], 1e-6f));
  lg[1] = logf(fmaxf(imp[b * NHEADS + ((q2 + 1) & 15)], 1e-6f));
  lg[2] = logf(fmaxf(imp[b * NHEADS + ((q2 + 8) & 15)], 1e-6f));
  lg[3] = logf(fmaxf(imp[b * NHEADS + ((q2 + 9) & 15)], 1e-6f));

  float m0 = -INFINITY, m1 = -INFINITY, l0 = 0.0f, l1 = 0.0f;
  float y[8][4];
#pragma unroll
  for (int nf = 0; nf < 8; nf++)
#pragma unroll
    for (int q = 0; q < 4; q++) y[nf][q] = 0.0f;

  const int NT = SKV / 64;
  for (int t = 0; t < NT; t++) {
    const int cur = t & 1;
    if (t + 1 < NT) F_PREFETCH(t + 1, cur ^ 1);
    MBARRIER_WAIT_PARITY(sb + FS_MBAR + cur * 8, (t >> 1) & 1);
    const uint32_t st = sb + (uint32_t)cur * FS_STAGE;

    // ---- S = Q K^T (bf16x3) ----
    float s[8][4];
#pragma unroll
    for (int nf = 0; nf < 8; nf++)
#pragma unroll
      for (int q = 0; q < 4; q++) s[nf][q] = 0.0f;
#pragma unroll
    for (int kc = 0; kc < 4; kc++) {
#pragma unroll
      for (int n2 = 0; n2 < 4; n2++) {
        int r = n2 * 16 + nof;
        int seg = 2 * kc + (kof2 >> 3);
        uint32_t bd = st + (uint32_t)(r * 128 + ((seg ^ (r & 7)) << 4));
        uint32_t bh[4], bl[4];
        ldsm4(bh, bd);
        ldsm4(bl, bd + FS_TILE);
#pragma unroll
        for (int hh = 0; hh < 2; hh++) {
          mma16816(s[n2 * 2 + hh], qfa[kc], &bh[2 * hh]);
          mma16816(s[n2 * 2 + hh], qfa[kc], &bl[2 * hh]);
          mma16816(s[n2 * 2 + hh], qfb[kc], &bh[2 * hh]);
        }
      }
    }

    // ---- scale + mask + online softmax ----
    float mt0 = -INFINITY, mt1 = -INFINITY;
#pragma unroll
    for (int nf = 0; nf < 8; nf++) {
      const int p = (nf & 1) * 2;
      s[nf][0] = s[nf][0] * 0.125f + lg[p];
      s[nf][1] = s[nf][1] * 0.125f + lg[p + 1];
      s[nf][2] = s[nf][2] * 0.125f + lg[p];
      s[nf][3] = s[nf][3] * 0.125f + lg[p + 1];
      mt0 = fmaxf(mt0, fmaxf(s[nf][0], s[nf][1]));
      mt1 = fmaxf(mt1, fmaxf(s[nf][2], s[nf][3]));
    }
    mt0 = fmaxf(mt0, __shfl_xor_sync(0xffffffffu, mt0, 1));
    mt0 = fmaxf(mt0, __shfl_xor_sync(0xffffffffu, mt0, 2));
    mt1 = fmaxf(mt1, __shfl_xor_sync(0xffffffffu, mt1, 1));
    mt1 = fmaxf(mt1, __shfl_xor_sync(0xffffffffu, mt1, 2));

    float mn0 = fmaxf(m0, mt0), mn1 = fmaxf(m1, mt1);
    float c0 = __expf(m0 - mn0), c1 = __expf(m1 - mn1);
    m0 = mn0; m1 = mn1;

    uint32_t ph[4][4], pl[4][4];
    float r0 = 0.0f, r1 = 0.0f;
#pragma unroll
    for (int nf = 0; nf < 8; nf++) {
      float p0 = __expf(s[nf][0] - m0);
      float p1 = __expf(s[nf][1] - m0);
      float p2 = __expf(s[nf][2] - m1);
      float p3 = __expf(s[nf][3] - m1);
      r0 += p0 + p1;
      r1 += p2 + p3;
      const int kc = nf >> 1, o = (nf & 1) * 2;
      pack_hilo(p0, p1, ph[kc][o], pl[kc][o]);
      pack_hilo(p2, p3, ph[kc][o + 1], pl[kc][o + 1]);
    }
    r0 += __shfl_xor_sync(0xffffffffu, r0, 1);
    r0 += __shfl_xor_sync(0xffffffffu, r0, 2);
    r1 += __shfl_xor_sync(0xffffffffu, r1, 1);
    r1 += __shfl_xor_sync(0xffffffffu, r1, 2);
    l0 = l0 * c0 + r0;
    l1 = l1 * c1 + r1;
#pragma unroll
    for (int nf = 0; nf < 8; nf++) {
      y[nf][0] *= c0; y[nf][1] *= c0;
      y[nf][2] *= c1; y[nf][3] *= c1;
    }

    // ---- y += P V (bf16x3) ----
#pragma unroll
    for (int kc = 0; kc < 4; kc++) {
#pragma unroll
      for (int n2 = 0; n2 < 4; n2++) {
        int r = n2 * 16 + nof;
        int seg = 2 * kc + (kof2 >> 3);
        uint32_t bd = st + 2 * FS_TILE +
                      (uint32_t)(r * 128 + ((seg ^ (r & 7)) << 4));
        uint32_t vh[4], vl[4];
        ldsm4(vh, bd);
        ldsm4(vl, bd + FS_TILE);
#pragma unroll
        for (int hh = 0; hh < 2; hh++) {
          mma16816(y[n2 * 2 + hh], ph[kc], &vh[2 * hh]);
          mma16816(y[n2 * 2 + hh], ph[kc], &vl[2 * hh]);
          mma16816(y[n2 * 2 + hh], pl[kc], &vh[2 * hh]);
        }
      }
    }
    __syncthreads();   // all warps done with stage cur before it is refilled
  }

  // ---- epilogue ----
  const float i0 = 1.0f / l0, i1 = 1.0f / l1;
  const int row0 = q0 + wm + (lane >> 2);
#pragma unroll
  for (int nf = 0; nf < 8; nf++) {
    int d0 = 8 * nf + q2;
    *(float2*)(Y + ((size_t)b * TQ + row0) * D_MODEL + h * HDIM + d0) =
        make_float2(y[nf][0] * i0, y[nf][1] * i0);
    *(float2*)(Y + ((size_t)b * TQ + row0 + 8) * D_MODEL + h * HDIM + d0) =
        make_float2(y[nf][2] * i1, y[nf][3] * i1);
  }
}

// ---------------------------------------------------------------------------
extern "C" void kernel_launch(void* const* d_in, const int* in_sizes, int n_in,
                              void* d_out, int out_size) {
  const float* query     = (const float*)d_in[0];
  const float* key_value = (const float*)d_in[1];
  const float* imp       = (const float*)d_in[2];
  const float* Wq        = (const float*)d_in[3];
  const float* Wk        = (const float*)d_in[4];
  const float* Wv        = (const float*)d_in[5];
  const float* Wo        = (const float*)d_in[6];
  float* out = (float*)d_out;

  float *Qb, *Kb, *Vb, *Yb;
  cudaGetSymbolAddress((void**)&Qb, g_Q);
  cudaGetSymbolAddress((void**)&Kb, g_K);
  cudaGetSymbolAddress((void**)&Vb, g_V);
  cudaGetSymbolAddress((void**)&Yb, g_Y);

  __nv_bfloat16 *qh, *ql, *kvh, *kvl, *yh, *yl, *wh, *wl, *kfh, *kfl, *vth, *vtl;
  cudaGetSymbolAddress((void**)&qh, g_qh);
  cudaGetSymbolAddress((void**)&ql, g_ql);
  cudaGetSymbolAddress((void**)&kvh, g_kvh);
  cudaGetSymbolAddress((void**)&kvl, g_kvl);
  cudaGetSymbolAddress((void**)&yh, g_yh);
  cudaGetSymbolAddress((void**)&yl, g_yl);
  cudaGetSymbolAddress((void**)&wh, g_wh);
  cudaGetSymbolAddress((void**)&wl, g_wl);
  cudaGetSymbolAddress((void**)&kfh, g_kfh);
  cudaGetSymbolAddress((void**)&kfl, g_kfl);
  cudaGetSymbolAddress((void**)&vth, g_vth);
  cudaGetSymbolAddress((void**)&vtl, g_vtl);
  const size_t WSZ = (size_t)D_MODEL * D_MODEL;

  cudaFuncSetAttribute(gemm_bulk,
                       cudaFuncAttributeMaxDynamicSharedMemorySize, GS_SMEM);
  cudaFuncSetAttribute(flash_bulk,
                       cudaFuncAttributeMaxDynamicSharedMemorySize, FS_SMEM);

  const int NQ = BATCH * TQ * D_MODEL;
  const int NKV = BATCH * SKV * D_MODEL;
  const int NW = D_MODEL * D_MODEL;

  // Pack raw inputs + weights into GEMM operand tiles (bf16 hi/lo).
  cvt_pack_gemm<<<NQ / 2048, 256>>>(query, qh, ql, NQ);
  cvt_pack_gemm<<<NKV / 2048, 256>>>(key_value, kvh, kvl, NKV);
  cvt_pack_gemm<<<NW / 2048, 256>>>(Wq, wh + 0 * WSZ, wl + 0 * WSZ, NW);
  cvt_pack_gemm<<<NW / 2048, 256>>>(Wk, wh + 1 * WSZ, wl + 1 * WSZ, NW);
  cvt_pack_gemm<<<NW / 2048, 256>>>(Wv, wh + 2 * WSZ, wl + 2 * WSZ, NW);
  cvt_pack_gemm<<<NW / 2048, 256>>>(Wo, wh + 3 * WSZ, wl + 3 * WSZ, NW);

  // Projections (HMMA bf16x3, bulk-DMA operands).
  gemm_bulk<<<dim3(8, 32), 256, GS_SMEM>>>(
      qh, ql, wh + 0 * WSZ, wl + 0 * WSZ, Qb, BATCH * TQ, D_MODEL, D_MODEL);
  gemm_bulk<<<dim3(8, 64), 256, GS_SMEM>>>(
      kvh, kvl, wh + 1 * WSZ, wl + 1 * WSZ, Kb, BATCH * SKV, D_MODEL, D_MODEL);
  gemm_bulk<<<dim3(8, 64), 256, GS_SMEM>>>(
      kvh, kvl, wh + 2 * WSZ, wl + 2 * WSZ, Vb, BATCH * SKV, D_MODEL, D_MODEL);

  // Pack projections into flash tile layouts (qh/ql reused: Q-GEMM done).
  qpack_flash<<<(BATCH * TQ * 128) / 256, 256>>>(Qb, qh, ql);
  kpack_flash<<<(BATCH * SKV * 128) / 256, 256>>>(Kb, kfh, kfl);
  vpack_flash<<<dim3(SKV / 64, NHEADS, BATCH), 256>>>(Vb, vth, vtl);

  // Flash attention (bulk-DMA K/V).
  flash_bulk<<<dim3(TQ / 128, NHEADS, BATCH), 256, FS_SMEM>>>(
      qh, ql, kfh, kfl, vth, vtl, imp, Yb);

  // Output projection.
  cvt_pack_gemm<<<NQ / 2048, 256>>>(Yb, yh, yl, NQ);
  gemm_bulk<<<dim3(8, 32), 256, GS_SMEM>>>(
      yh, yl, wh + 3 * WSZ, wl + 3 * WSZ, out, BATCH * TQ, D_MODEL, D_MODEL);
}

// round 7
// speedup vs baseline: 3.3758x; 1.0152x over previous
#include <cuda_runtime.h>
#include <cuda_bf16.h>
#include <cstdint>
#include <math.h>

#define D_MODEL 1024
#define BATCH   2
#define TQ      2048
#define SKV     4096
#define NHEADS  16
#define HDIM    64

// ---------------- scratch (no cudaMalloc allowed) ----------------
// qh/ql: raw-query GEMM-A pack, then reused as flash-Y GEMM-A pack.
// yh/yl: flash-Q packed tiles (Q-GEMM output).
__device__ __align__(256) __nv_bfloat16 g_qh[(size_t)BATCH * TQ  * D_MODEL];
__device__ __align__(256) __nv_bfloat16 g_ql[(size_t)BATCH * TQ  * D_MODEL];
__device__ __align__(256) __nv_bfloat16 g_kvh[(size_t)BATCH * SKV * D_MODEL];
__device__ __align__(256) __nv_bfloat16 g_kvl[(size_t)BATCH * SKV * D_MODEL];
__device__ __align__(256) __nv_bfloat16 g_yh[(size_t)BATCH * TQ  * D_MODEL];
__device__ __align__(256) __nv_bfloat16 g_yl[(size_t)BATCH * TQ  * D_MODEL];
__device__ __align__(256) __nv_bfloat16 g_wh[4][(size_t)D_MODEL * D_MODEL];
__device__ __align__(256) __nv_bfloat16 g_wl[4][(size_t)D_MODEL * D_MODEL];
__device__ __align__(256) __nv_bfloat16 g_kfh[(size_t)BATCH * SKV * D_MODEL];
__device__ __align__(256) __nv_bfloat16 g_kfl[(size_t)BATCH * SKV * D_MODEL];
__device__ __align__(256) __nv_bfloat16 g_vth[(size_t)BATCH * NHEADS * HDIM * SKV];
__device__ __align__(256) __nv_bfloat16 g_vtl[(size_t)BATCH * NHEADS * HDIM * SKV];

// ---------------- primitives ----------------
__device__ __forceinline__ uint32_t smem_u32(const void* p) {
  uint32_t a;
  asm("{ .reg .u64 t; cvta.to.shared.u64 t, %1; cvt.u32.u64 %0, t; }"
      : "=r"(a) : "l"(p));
  return a;
}
__device__ __forceinline__ void ldsm4(uint32_t* r, uint32_t a) {
  asm volatile("ldmatrix.sync.aligned.m8n8.x4.shared.b16 {%0,%1,%2,%3}, [%4];"
               : "=r"(r[0]), "=r"(r[1]), "=r"(r[2]), "=r"(r[3]) : "r"(a));
}
__device__ __forceinline__ void mma16816(float* d, const uint32_t* a,
                                         const uint32_t* b) {
  asm volatile(
      "mma.sync.aligned.m16n8k16.row.col.f32.bf16.bf16.f32 "
      "{%0,%1,%2,%3}, {%4,%5,%6,%7}, {%8,%9}, {%0,%1,%2,%3};"
      : "+f"(d[0]), "+f"(d[1]), "+f"(d[2]), "+f"(d[3])
      : "r"(a[0]), "r"(a[1]), "r"(a[2]), "r"(a[3]), "r"(b[0]), "r"(b[1]));
}
__device__ __forceinline__ void cp16(uint32_t dst, const void* src) {
  asm volatile("cp.async.cg.shared.global [%0], [%1], 16;" :: "r"(dst), "l"(src));
}
#define CP_COMMIT() asm volatile("cp.async.commit_group;")

__device__ __forceinline__ void bulk_g2s(uint32_t dst, const void* src,
                                         uint32_t bytes, uint32_t mbar) {
  asm volatile(
      "cp.async.bulk.shared::cluster.global.mbarrier::complete_tx::bytes "
      "[%0], [%1], %2, [%3];"
      :: "r"(dst), "l"(src), "r"(bytes), "r"(mbar) : "memory");
}
#define MBARRIER_INIT(mbar, count)                                            \
  asm volatile("mbarrier.init.shared.b64 [%0], %1;"                           \
               :: "r"((uint32_t)(mbar)), "r"((uint32_t)(count)) : "memory")
#define MBARRIER_EXPECT_TX(mbar, tx)                                          \
  asm volatile("mbarrier.arrive.expect_tx.shared.b64 _, [%0], %1;"            \
               :: "r"((uint32_t)(mbar)), "r"((uint32_t)(tx)) : "memory")
#define MBARRIER_WAIT_PARITY(mbar_addr, phase_parity) do {                    \
  uint32_t _mbar = (uint32_t)(mbar_addr);                                     \
  uint32_t _par = (uint32_t)(phase_parity);                                   \
  uint32_t _done;                                                             \
  asm volatile(                                                               \
      "{\n\t.reg .pred p;\n\t"                                                \
      "mbarrier.try_wait.parity.acquire.cta.shared::cta.b64 p, [%1], %2;\n\t" \
      "selp.b32 %0, 1, 0, p;\n\t}"                                            \
      : "=r"(_done) : "r"(_mbar), "r"(_par) : "memory");                      \
  if (!_done) {                                                               \
    asm volatile(                                                             \
        "{\n\t.reg .pred P1;\n\t"                                             \
        "WAIT_LOOP_%=:\n\t"                                                   \
        "mbarrier.try_wait.parity.acquire.cta.shared::cta.b64 P1, [%0], %1, 0x989680;\n\t" \
        "@P1 bra.uni WAIT_DONE_%=;\n\t"                                       \
        "bra.uni WAIT_LOOP_%=;\n\t"                                           \
        "WAIT_DONE_%=:\n\t}"                                                  \
        :: "r"(_mbar), "r"(_par) : "memory");                                 \
  }                                                                           \
} while (0)

__device__ __forceinline__ void pack_hilo(float p0, float p1, uint32_t& hi,
                                          uint32_t& lo) {
  __nv_bfloat162 h = __floats2bfloat162_rn(p0, p1);
  float r0 = p0 - __bfloat162float(h.x);
  float r1 = p1 - __bfloat162float(h.y);
  __nv_bfloat162 l = __floats2bfloat162_rn(r0, r1);
  hi = *reinterpret_cast<uint32_t*>(&h);
  lo = *reinterpret_cast<uint32_t*>(&l);
}

// ---------------------------------------------------------------------------
// fp32 [M,1024] row-major -> packed GEMM tiles [mb][kc][128x32 halves],
// 64B rows, seg ^= ((r>>1)&3). n multiple of 2048.
// ---------------------------------------------------------------------------
__global__ void cvt_pack_gemm(const float* __restrict__ x,
                              __nv_bfloat16* __restrict__ ph,
                              __nv_bfloat16* __restrict__ pl, int n) {
  int i = blockIdx.x * blockDim.x + threadIdx.x;
  if (i * 8 >= n) return;
  const float* src = x + (size_t)i * 8;
  float4 a = *(const float4*)src;
  float4 b = *(const float4*)(src + 4);
  uint32_t h0, h1, h2, h3, l0, l1, l2, l3;
  pack_hilo(a.x, a.y, h0, l0);
  pack_hilo(a.z, a.w, h1, l1);
  pack_hilo(b.x, b.y, h2, l2);
  pack_hilo(b.z, b.w, h3, l3);
  int m = (i * 8) >> 10, k = (i * 8) & 1023;
  int r = m & 127, mb = m >> 7, kc = k >> 5, seg = (k >> 3) & 3;
  size_t t = ((size_t)mb * 32 + kc) * 4096 + r * 32 +
             ((seg ^ ((r >> 1) & 3)) << 3);
  *(uint4*)(ph + t) = make_uint4(h0, h1, h2, h3);
  *(uint4*)(pl + t) = make_uint4(l0, l1, l2, l3);
}

// All 4 weights packed in one launch. 4 * 131072 groups of 8.
__global__ void wpack4(const float* __restrict__ w0, const float* __restrict__ w1,
                       const float* __restrict__ w2, const float* __restrict__ w3,
                       __nv_bfloat16* __restrict__ ph,
                       __nv_bfloat16* __restrict__ pl) {
  int i = blockIdx.x * blockDim.x + threadIdx.x;
  int w = i >> 17, li = i & 131071;
  const float* src = (w == 0 ? w0 : w == 1 ? w1 : w == 2 ? w2 : w3) +
                     (size_t)li * 8;
  float4 a = *(const float4*)src;
  float4 b = *(const float4*)(src + 4);
  uint32_t h0, h1, h2, h3, l0, l1, l2, l3;
  pack_hilo(a.x, a.y, h0, l0);
  pack_hilo(a.z, a.w, h1, l1);
  pack_hilo(b.x, b.y, h2, l2);
  pack_hilo(b.z, b.w, h3, l3);
  int e = li * 8;
  int m = e >> 10, k = e & 1023;
  int r = m & 127, mb = m >> 7, kc = k >> 5, seg = (k >> 3) & 3;
  size_t t = (size_t)w * D_MODEL * D_MODEL +
             ((size_t)mb * 32 + kc) * 4096 + r * 32 +
             ((seg ^ ((r >> 1) & 3)) << 3);
  *(uint4*)(ph + t) = make_uint4(h0, h1, h2, h3);
  *(uint4*)(pl + t) = make_uint4(l0, l1, l2, l3);
}

// ---------------------------------------------------------------------------
// bf16x3 NT GEMM, bulk-DMA operands, templated epilogue:
// MODE 0: fp32 C row-major.
// MODE 1: flash-Q pack  (rows=q over B*TQ,  cols=dmodel)
// MODE 2: flash-K pack  (rows=s over B*SKV, cols=dmodel)
// MODE 3: flash-V pack  (rows=dmodel (transposed GEMM), cols=(b,s))
// ---------------------------------------------------------------------------
#define GS_TILE  8192
#define GS_STAGE 32768
#define GS_MBAR  65536
#define GS_SMEM  65664

template <int MODE>
__global__ __launch_bounds__(256, 2)
void gemm_bulk_t(const __nv_bfloat16* __restrict__ Ah,
                 const __nv_bfloat16* __restrict__ Al,
                 const __nv_bfloat16* __restrict__ Bh,
                 const __nv_bfloat16* __restrict__ Bl,
                 float* __restrict__ C,
                 __nv_bfloat16* __restrict__ Ph,
                 __nv_bfloat16* __restrict__ Pl, int M, int N, int K) {
  extern __shared__ __align__(128) char sm[];
  const uint32_t sb = smem_u32(sm);
  const int tid = threadIdx.x, lane = tid & 31, warp = tid >> 5;
  const int wm = (warp & 3) * 32;
  const int wn = (warp >> 2) * 64;
  const int bm = blockIdx.y * 128;
  const int bn = blockIdx.x * 128;
  const int nch = K >> 5;
  const int mb = bm >> 7, nb = bn >> 7;

  float acc[2][8][4];
#pragma unroll
  for (int mi = 0; mi < 2; mi++)
#pragma unroll
    for (int nj = 0; nj < 8; nj++)
#pragma unroll
      for (int q = 0; q < 4; q++) acc[mi][nj][q] = 0.0f;

  if (tid == 0) {
    MBARRIER_INIT(sb + GS_MBAR, 1);
    MBARRIER_INIT(sb + GS_MBAR + 8, 1);
  }
  __syncthreads();

#define G_PREFETCH(c_, s_) do {                                               \
    if (tid == 0) {                                                           \
      uint32_t mb_ = sb + GS_MBAR + (s_) * 8;                                 \
      MBARRIER_EXPECT_TX(mb_, 32768u);                                        \
      uint32_t d_ = sb + (uint32_t)(s_) * GS_STAGE;                           \
      bulk_g2s(d_,             Ah + ((size_t)(mb * nch + (c_))) * 4096, 8192u, mb_); \
      bulk_g2s(d_ + GS_TILE,   Al + ((size_t)(mb * nch + (c_))) * 4096, 8192u, mb_); \
      bulk_g2s(d_ + 2*GS_TILE, Bh + ((size_t)(nb * nch + (c_))) * 4096, 8192u, mb_); \
      bulk_g2s(d_ + 3*GS_TILE, Bl + ((size_t)(nb * nch + (c_))) * 4096, 8192u, mb_); \
    }                                                                         \
  } while (0)

  G_PREFETCH(0, 0);

  const int ar = lane & 15;
  const int ac = ((lane >> 4) & 1) * 8;
  const int nof = ((lane >> 4) & 1) * 8 + (lane & 7);
  const int kof2 = ((lane >> 3) & 1) * 8;

  for (int c = 0; c < nch; c++) {
    const int cur = c & 1;
    if (c + 1 < nch) G_PREFETCH(c + 1, cur ^ 1);
    MBARRIER_WAIT_PARITY(sb + GS_MBAR + cur * 8, (c >> 1) & 1);

    const uint32_t st = sb + (uint32_t)cur * GS_STAGE;
#pragma unroll
    for (int ks = 0; ks < 2; ks++) {
      const int k0 = ks * 16;
      uint32_t afh[2][4], afl[2][4];
#pragma unroll
      for (int mi = 0; mi < 2; mi++) {
        int r = wm + mi * 16 + ar;
        int seg = (k0 + ac) >> 3;
        uint32_t ad = st + (uint32_t)(r * 64 + ((seg ^ ((r >> 1) & 3)) << 4));
        ldsm4(afh[mi], ad);
        ldsm4(afl[mi], ad + GS_TILE);
      }
#pragma unroll
      for (int ni = 0; ni < 4; ni++) {
        int rb = wn + ni * 16 + nof;
        int segb = (k0 + kof2) >> 3;
        uint32_t bd = st + 2 * GS_TILE +
                      (uint32_t)(rb * 64 + ((segb ^ ((rb >> 1) & 3)) << 4));
        uint32_t bh[4], bl[4];
        ldsm4(bh, bd);
        ldsm4(bl, bd + GS_TILE);
#pragma unroll
        for (int mi = 0; mi < 2; mi++)
#pragma unroll
          for (int hh = 0; hh < 2; hh++) {
            int nj = ni * 2 + hh;
            mma16816(acc[mi][nj], afh[mi], &bh[2 * hh]);
            mma16816(acc[mi][nj], afh[mi], &bl[2 * hh]);
            mma16816(acc[mi][nj], afl[mi], &bh[2 * hh]);
          }
      }
    }
    __syncthreads();
  }

  // ---- epilogue ----
  const int crow = lane >> 2;
  const int ccol = (lane & 3) * 2;
#pragma unroll
  for (int mi = 0; mi < 2; mi++)
#pragma unroll
    for (int nj = 0; nj < 8; nj++) {
      int m0 = bm + wm + mi * 16 + crow;
      int cc = bn + wn + nj * 8 + ccol;
      if (MODE == 0) {
        *(float2*)(C + (size_t)m0 * N + cc) =
            make_float2(acc[mi][nj][0], acc[mi][nj][1]);
        *(float2*)(C + (size_t)(m0 + 8) * N + cc) =
            make_float2(acc[mi][nj][2], acc[mi][nj][3]);
      } else {
#pragma unroll
        for (int half = 0; half < 2; half++) {
          int m = m0 + half * 8;
          float v0 = acc[mi][nj][half * 2], v1 = acc[mi][nj][half * 2 + 1];
          size_t t;
          if (MODE == 1) {            // flash-Q: b=m>>11, q=m&2047
            int b = m >> 11, q = m & 2047;
            int h = cc >> 6, dd = cc & 63;
            t = ((size_t)(b * 16 + h) * 16 + (q >> 7)) * 8192 +
                (size_t)(q & 127) * 64 + (((dd >> 3) ^ (q & 7)) << 3) + (dd & 7);
          } else if (MODE == 2) {     // flash-K: b=m>>12, s=m&4095
            int b = m >> 12, s = m & 4095;
            int h = cc >> 6, dd = cc & 63;
            t = ((size_t)(b * 16 + h) * 64 + (s >> 6)) * 4096 +
                (size_t)(s & 63) * 64 + (((dd >> 3) ^ (s & 7)) << 3) + (dd & 7);
          } else {                    // MODE 3, flash-V: m=dmodel, cc=(b,s)
            int h = m >> 6, dr = m & 63;
            int b = cc >> 12, s = cc & 4095;
            t = ((size_t)(b * 16 + h) * 64 + (s >> 6)) * 4096 +
                (size_t)dr * 64 + ((((s >> 3) & 7) ^ (dr & 7)) << 3) + (s & 7);
          }
          uint32_t hi, lo;
          pack_hilo(v0, v1, hi, lo);
          *(uint32_t*)(Ph + t) = hi;
          *(uint32_t*)(Pl + t) = lo;
        }
      }
    }
}

// ---------------------------------------------------------------------------
// HMMA flash attention, bf16x3 QK^T and PV, bulk-DMA K/V, P in registers.
// Epilogue writes Y directly as GEMM-A packed hi/lo tiles.
// ---------------------------------------------------------------------------
#define FS_TILE  8192
#define FS_STAGE 32768
#define FS_QOFF  65536
#define FS_MBAR  98304
#define FS_SMEM  98432

__global__ __launch_bounds__(256)
void flash_bulk(const __nv_bfloat16* __restrict__ qfh,
                const __nv_bfloat16* __restrict__ qfl,
                const __nv_bfloat16* __restrict__ kfh,
                const __nv_bfloat16* __restrict__ kfl,
                const __nv_bfloat16* __restrict__ vth,
                const __nv_bfloat16* __restrict__ vtl,
                const float* __restrict__ imp,
                __nv_bfloat16* __restrict__ Yh,
                __nv_bfloat16* __restrict__ Yl) {
  extern __shared__ __align__(128) char fsm[];
  const uint32_t sb = smem_u32(fsm);
  const int b = blockIdx.z, h = blockIdx.y, qb = blockIdx.x;
  const int q0 = qb * 128;
  const int tid = threadIdx.x, lane = tid & 31, warp = tid >> 5;
  const int wm = warp * 16;

  if (tid == 0) {
    MBARRIER_INIT(sb + FS_MBAR, 1);
    MBARRIER_INIT(sb + FS_MBAR + 8, 1);
  }
  {
    const __nv_bfloat16* qsrc = qfh + ((size_t)(b * 16 + h) * 16 + qb) * 8192;
    const __nv_bfloat16* qsrc2 = qfl + ((size_t)(b * 16 + h) * 16 + qb) * 8192;
#pragma unroll
    for (int j = 0; j < 4; j++) {
      int idx = tid + j * 256;
      cp16(sb + FS_QOFF + idx * 16, qsrc + idx * 8);
      cp16(sb + FS_QOFF + 16384 + idx * 16, qsrc2 + idx * 8);
    }
  }
  CP_COMMIT();
  __syncthreads();

  const __nv_bfloat16* Kb = kfh + ((size_t)(b * 16 + h) * 64) * 4096;
  const __nv_bfloat16* Kb2 = kfl + ((size_t)(b * 16 + h) * 64) * 4096;
  const __nv_bfloat16* Vb = vth + ((size_t)(b * 16 + h) * 64) * 4096;
  const __nv_bfloat16* Vb2 = vtl + ((size_t)(b * 16 + h) * 64) * 4096;

#define F_PREFETCH(t_, s_) do {                                               \
    if (tid == 0) {                                                           \
      uint32_t mb_ = sb + FS_MBAR + (s_) * 8;                                 \
      MBARRIER_EXPECT_TX(mb_, 32768u);                                        \
      uint32_t d_ = sb + (uint32_t)(s_) * FS_STAGE;                           \
      bulk_g2s(d_,             Kb  + (size_t)(t_) * 4096, 8192u, mb_);        \
      bulk_g2s(d_ + FS_TILE,   Kb2 + (size_t)(t_) * 4096, 8192u, mb_);        \
      bulk_g2s(d_ + 2*FS_TILE, Vb  + (size_t)(t_) * 4096, 8192u, mb_);        \
      bulk_g2s(d_ + 3*FS_TILE, Vb2 + (size_t)(t_) * 4096, 8192u, mb_);        \
    }                                                                         \
  } while (0)

  F_PREFETCH(0, 0);

  const int ar = lane & 15;
  const int ac = ((lane >> 4) & 1) * 8;
  const int nof = ((lane >> 4) & 1) * 8 + (lane & 7);
  const int kof2 = ((lane >> 3) & 1) * 8;

  asm volatile("cp.async.wait_group 0;");
  __syncthreads();
  uint32_t qfa[4][4], qfb[4][4];
#pragma unroll
  for (int kc = 0; kc < 4; kc++) {
    int r = wm + ar;
    int seg = 2 * kc + (ac >> 3);
    uint32_t ad = sb + FS_QOFF + (uint32_t)(r * 128 + ((seg ^ (r & 7)) << 4));
    ldsm4(qfa[kc], ad);
    ldsm4(qfb[kc], ad + 16384);
  }

  const int q2 = (lane & 3) * 2;
  float lg[4];
  lg[0] = logf(fmaxf(imp[b * NHEADS + (q2 & 15)], 1e-6f));
  lg[1] = logf(fmaxf(imp[b * NHEADS + ((q2 + 1) & 15)], 1e-6f));
  lg[2] = logf(fmaxf(imp[b * NHEADS + ((q2 + 8) & 15)], 1e-6f));
  lg[3] = logf(fmaxf(imp[b * NHEADS + ((q2 + 9) & 15)], 1e-6f));

  float m0 = -INFINITY, m1 = -INFINITY, l0 = 0.0f, l1 = 0.0f;
  float y[8][4];
#pragma unroll
  for (int nf = 0; nf < 8; nf++)
#pragma unroll
    for (int q = 0; q < 4; q++) y[nf][q] = 0.0f;

  const int NT = SKV / 64;
  for (int t = 0; t < NT; t++) {
    const int cur = t & 1;
    if (t + 1 < NT) F_PREFETCH(t + 1, cur ^ 1);
    MBARRIER_WAIT_PARITY(sb + FS_MBAR + cur * 8, (t >> 1) & 1);
    const uint32_t st = sb + (uint32_t)cur * FS_STAGE;

    float s[8][4];
#pragma unroll
    for (int nf = 0; nf < 8; nf++)
#pragma unroll
      for (int q = 0; q < 4; q++) s[nf][q] = 0.0f;
#pragma unroll
    for (int kc = 0; kc < 4; kc++) {
#pragma unroll
      for (int n2 = 0; n2 < 4; n2++) {
        int r = n2 * 16 + nof;
        int seg = 2 * kc + (kof2 >> 3);
        uint32_t bd = st + (uint32_t)(r * 128 + ((seg ^ (r & 7)) << 4));
        uint32_t bh[4], bl[4];
        ldsm4(bh, bd);
        ldsm4(bl, bd + FS_TILE);
#pragma unroll
        for (int hh = 0; hh < 2; hh++) {
          mma16816(s[n2 * 2 + hh], qfa[kc], &bh[2 * hh]);
          mma16816(s[n2 * 2 + hh], qfa[kc], &bl[2 * hh]);
          mma16816(s[n2 * 2 + hh], qfb[kc], &bh[2 * hh]);
        }
      }
    }

    float mt0 = -INFINITY, mt1 = -INFINITY;
#pragma unroll
    for (int nf = 0; nf < 8; nf++) {
      const int p = (nf & 1) * 2;
      s[nf][0] = s[nf][0] * 0.125f + lg[p];
      s[nf][1] = s[nf][1] * 0.125f + lg[p + 1];
      s[nf][2] = s[nf][2] * 0.125f + lg[p];
      s[nf][3] = s[nf][3] * 0.125f + lg[p + 1];
      mt0 = fmaxf(mt0, fmaxf(s[nf][0], s[nf][1]));
      mt1 = fmaxf(mt1, fmaxf(s[nf][2], s[nf][3]));
    }
    mt0 = fmaxf(mt0, __shfl_xor_sync(0xffffffffu, mt0, 1));
    mt0 = fmaxf(mt0, __shfl_xor_sync(0xffffffffu, mt0, 2));
    mt1 = fmaxf(mt1, __shfl_xor_sync(0xffffffffu, mt1, 1));
    mt1 = fmaxf(mt1, __shfl_xor_sync(0xffffffffu, mt1, 2));

    float mn0 = fmaxf(m0, mt0), mn1 = fmaxf(m1, mt1);
    float c0 = __expf(m0 - mn0), c1 = __expf(m1 - mn1);
    m0 = mn0; m1 = mn1;

    uint32_t ph[4][4], pl[4][4];
    float r0 = 0.0f, r1 = 0.0f;
#pragma unroll
    for (int nf = 0; nf < 8; nf++) {
      float p0 = __expf(s[nf][0] - m0);
      float p1 = __expf(s[nf][1] - m0);
      float p2 = __expf(s[nf][2] - m1);
      float p3 = __expf(s[nf][3] - m1);
      r0 += p0 + p1;
      r1 += p2 + p3;
      const int kc = nf >> 1, o = (nf & 1) * 2;
      pack_hilo(p0, p1, ph[kc][o], pl[kc][o]);
      pack_hilo(p2, p3, ph[kc][o + 1], pl[kc][o + 1]);
    }
    r0 += __shfl_xor_sync(0xffffffffu, r0, 1);
    r0 += __shfl_xor_sync(0xffffffffu, r0, 2);
    r1 += __shfl_xor_sync(0xffffffffu, r1, 1);
    r1 += __shfl_xor_sync(0xffffffffu, r1, 2);
    l0 = l0 * c0 + r0;
    l1 = l1 * c1 + r1;
#pragma unroll
    for (int nf = 0; nf < 8; nf++) {
      y[nf][0] *= c0; y[nf][1] *= c0;
      y[nf][2] *= c1; y[nf][3] *= c1;
    }

#pragma unroll
    for (int kc = 0; kc < 4; kc++) {
#pragma unroll
      for (int n2 = 0; n2 < 4; n2++) {
        int r = n2 * 16 + nof;
        int seg = 2 * kc + (kof2 >> 3);
        uint32_t bd = st + 2 * FS_TILE +
                      (uint32_t)(r * 128 + ((seg ^ (r & 7)) << 4));
        uint32_t vh[4], vl[4];
        ldsm4(vh, bd);
        ldsm4(vl, bd + FS_TILE);
#pragma unroll
        for (int hh = 0; hh < 2; hh++) {
          mma16816(y[n2 * 2 + hh], ph[kc], &vh[2 * hh]);
          mma16816(y[n2 * 2 + hh], ph[kc], &vl[2 * hh]);
          mma16816(y[n2 * 2 + hh], pl[kc], &vh[2 * hh]);
        }
      }
    }
    __syncthreads();
  }

  // ---- epilogue: write Y as GEMM-A packed hi/lo tiles ----
  const float i0 = 1.0f / l0, i1 = 1.0f / l1;
  const int row0 = q0 + wm + (lane >> 2);
#pragma unroll
  for (int nf = 0; nf < 8; nf++) {
    int k = h * HDIM + 8 * nf + q2;
    int kc = k >> 5, seg0 = (k >> 3) & 3, klow = k & 7;
#pragma unroll
    for (int half = 0; half < 2; half++) {
      int m = b * TQ + row0 + half * 8;
      float v0 = y[nf][half * 2] * (half ? i1 : i0);
      float v1 = y[nf][half * 2 + 1] * (half ? i1 : i0);
      int r = m & 127, mb2 = m >> 7;
      size_t t = ((size_t)mb2 * 32 + kc) * 4096 + (size_t)r * 32 +
                 ((seg0 ^ ((r >> 1) & 3)) << 3) + klow;
      uint32_t hi, lo;
      pack_hilo(v0, v1, hi, lo);
      *(uint32_t*)(Yh + t) = hi;
      *(uint32_t*)(Yl + t) = lo;
    }
  }
}

// ---------------------------------------------------------------------------
extern "C" void kernel_launch(void* const* d_in, const int* in_sizes, int n_in,
                              void* d_out, int out_size) {
  const float* query     = (const float*)d_in[0];
  const float* key_value = (const float*)d_in[1];
  const float* imp       = (const float*)d_in[2];
  const float* Wq        = (const float*)d_in[3];
  const float* Wk        = (const float*)d_in[4];
  const float* Wv        = (const float*)d_in[5];
  const float* Wo        = (const float*)d_in[6];
  float* out = (float*)d_out;

  __nv_bfloat16 *qh, *ql, *kvh, *kvl, *yh, *yl, *wh, *wl, *kfh, *kfl, *vth, *vtl;
  cudaGetSymbolAddress((void**)&qh, g_qh);
  cudaGetSymbolAddress((void**)&ql, g_ql);
  cudaGetSymbolAddress((void**)&kvh, g_kvh);
  cudaGetSymbolAddress((void**)&kvl, g_kvl);
  cudaGetSymbolAddress((void**)&yh, g_yh);
  cudaGetSymbolAddress((void**)&yl, g_yl);
  cudaGetSymbolAddress((void**)&wh, g_wh);
  cudaGetSymbolAddress((void**)&wl, g_wl);
  cudaGetSymbolAddress((void**)&kfh, g_kfh);
  cudaGetSymbolAddress((void**)&kfl, g_kfl);
  cudaGetSymbolAddress((void**)&vth, g_vth);
  cudaGetSymbolAddress((void**)&vtl, g_vtl);
  const size_t WSZ = (size_t)D_MODEL * D_MODEL;

  cudaFuncSetAttribute(gemm_bulk_t<0>,
                       cudaFuncAttributeMaxDynamicSharedMemorySize, GS_SMEM);
  cudaFuncSetAttribute(gemm_bulk_t<1>,
                       cudaFuncAttributeMaxDynamicSharedMemorySize, GS_SMEM);
  cudaFuncSetAttribute(gemm_bulk_t<2>,
                       cudaFuncAttributeMaxDynamicSharedMemorySize, GS_SMEM);
  cudaFuncSetAttribute(gemm_bulk_t<3>,
                       cudaFuncAttributeMaxDynamicSharedMemorySize, GS_SMEM);
  cudaFuncSetAttribute(flash_bulk,
                       cudaFuncAttributeMaxDynamicSharedMemorySize, FS_SMEM);

  const int NQ = BATCH * TQ * D_MODEL;
  const int NKV = BATCH * SKV * D_MODEL;

  // Pack raw inputs + weights (bf16 hi/lo, GEMM-A tile layout).
  cvt_pack_gemm<<<NQ / 2048, 256>>>(query, qh, ql, NQ);
  cvt_pack_gemm<<<NKV / 2048, 256>>>(key_value, kvh, kvl, NKV);
  wpack4<<<2048, 256>>>(Wq, Wk, Wv, Wo, wh, wl);

  // Q projection -> flash-Q packed tiles (yh/yl).
  gemm_bulk_t<1><<<dim3(8, 32), 256, GS_SMEM>>>(
      qh, ql, wh + 0 * WSZ, wl + 0 * WSZ, nullptr, yh, yl,
      BATCH * TQ, D_MODEL, D_MODEL);
  // K projection -> flash-K packed tiles.
  gemm_bulk_t<2><<<dim3(8, 64), 256, GS_SMEM>>>(
      kvh, kvl, wh + 1 * WSZ, wl + 1 * WSZ, nullptr, kfh, kfl,
      BATCH * SKV, D_MODEL, D_MODEL);
  // V projection TRANSPOSED (A=Wv, B=kv) -> flash-V packed tiles.
  gemm_bulk_t<3><<<dim3(64, 8), 256, GS_SMEM>>>(
      wh + 2 * WSZ, wl + 2 * WSZ, kvh, kvl, nullptr, vth, vtl,
      D_MODEL, BATCH * SKV, D_MODEL);

  // Flash attention -> Y packed as GEMM-A tiles (qh/ql reused).
  flash_bulk<<<dim3(TQ / 128, NHEADS, BATCH), 256, FS_SMEM>>>(
      yh, yl, kfh, kfl, vth, vtl, imp, qh, ql);

  // Output projection -> fp32 out.
  gemm_bulk_t<0><<<dim3(8, 32), 256, GS_SMEM>>>(
      qh, ql, wh + 3 * WSZ, wl + 3 * WSZ, out, nullptr, nullptr,
      BATCH * TQ, D_MODEL, D_MODEL);
}

// round 8
// speedup vs baseline: 3.4342x; 1.0173x over previous
#include <cuda_runtime.h>
#include <cuda_bf16.h>
#include <cstdint>
#include <math.h>

#define D_MODEL 1024
#define BATCH   2
#define TQ      2048
#define SKV     4096
#define NHEADS  16
#define HDIM    64

// ---------------- scratch (no cudaMalloc allowed) ----------------
__device__ __align__(256) __nv_bfloat16 g_qh[(size_t)BATCH * TQ  * D_MODEL];
__device__ __align__(256) __nv_bfloat16 g_ql[(size_t)BATCH * TQ  * D_MODEL];
__device__ __align__(256) __nv_bfloat16 g_kvh[(size_t)BATCH * SKV * D_MODEL];
__device__ __align__(256) __nv_bfloat16 g_kvl[(size_t)BATCH * SKV * D_MODEL];
__device__ __align__(256) __nv_bfloat16 g_yh[(size_t)BATCH * TQ  * D_MODEL];
__device__ __align__(256) __nv_bfloat16 g_yl[(size_t)BATCH * TQ  * D_MODEL];
__device__ __align__(256) __nv_bfloat16 g_wh[4][(size_t)D_MODEL * D_MODEL];
__device__ __align__(256) __nv_bfloat16 g_wl[4][(size_t)D_MODEL * D_MODEL];
__device__ __align__(256) __nv_bfloat16 g_kfh[(size_t)BATCH * SKV * D_MODEL];
__device__ __align__(256) __nv_bfloat16 g_kfl[(size_t)BATCH * SKV * D_MODEL];
__device__ __align__(256) __nv_bfloat16 g_vth[(size_t)BATCH * NHEADS * HDIM * SKV];
__device__ __align__(256) __nv_bfloat16 g_vtl[(size_t)BATCH * NHEADS * HDIM * SKV];

// ---------------- primitives ----------------
__device__ __forceinline__ uint32_t smem_u32(const void* p) {
  uint32_t a;
  asm("{ .reg .u64 t; cvta.to.shared.u64 t, %1; cvt.u32.u64 %0, t; }"
      : "=r"(a) : "l"(p));
  return a;
}
__device__ __forceinline__ void ldsm4(uint32_t* r, uint32_t a) {
  asm volatile("ldmatrix.sync.aligned.m8n8.x4.shared.b16 {%0,%1,%2,%3}, [%4];"
               : "=r"(r[0]), "=r"(r[1]), "=r"(r[2]), "=r"(r[3]) : "r"(a));
}
__device__ __forceinline__ void mma16816(float* d, const uint32_t* a,
                                         const uint32_t* b) {
  asm volatile(
      "mma.sync.aligned.m16n8k16.row.col.f32.bf16.bf16.f32 "
      "{%0,%1,%2,%3}, {%4,%5,%6,%7}, {%8,%9}, {%0,%1,%2,%3};"
      : "+f"(d[0]), "+f"(d[1]), "+f"(d[2]), "+f"(d[3])
      : "r"(a[0]), "r"(a[1]), "r"(a[2]), "r"(a[3]), "r"(b[0]), "r"(b[1]));
}
__device__ __forceinline__ void cp16(uint32_t dst, const void* src) {
  asm volatile("cp.async.cg.shared.global [%0], [%1], 16;" :: "r"(dst), "l"(src));
}
#define CP_COMMIT() asm volatile("cp.async.commit_group;")

__device__ __forceinline__ void bulk_g2s(uint32_t dst, const void* src,
                                         uint32_t bytes, uint32_t mbar) {
  asm volatile(
      "cp.async.bulk.shared::cluster.global.mbarrier::complete_tx::bytes "
      "[%0], [%1], %2, [%3];"
      :: "r"(dst), "l"(src), "r"(bytes), "r"(mbar) : "memory");
}
#define MBARRIER_INIT(mbar, count)                                            \
  asm volatile("mbarrier.init.shared.b64 [%0], %1;"                           \
               :: "r"((uint32_t)(mbar)), "r"((uint32_t)(count)) : "memory")
#define MBARRIER_EXPECT_TX(mbar, tx)                                          \
  asm volatile("mbarrier.arrive.expect_tx.shared.b64 _, [%0], %1;"            \
               :: "r"((uint32_t)(mbar)), "r"((uint32_t)(tx)) : "memory")
#define MBARRIER_ARRIVE(mbar)                                                 \
  asm volatile("mbarrier.arrive.shared.b64 _, [%0];"                          \
               :: "r"((uint32_t)(mbar)) : "memory")
#define MBARRIER_WAIT_PARITY(mbar_addr, phase_parity) do {                    \
  uint32_t _mbar = (uint32_t)(mbar_addr);                                     \
  uint32_t _par = (uint32_t)(phase_parity);                                   \
  uint32_t _done;                                                             \
  asm volatile(                                                               \
      "{\n\t.reg .pred p;\n\t"                                                \
      "mbarrier.try_wait.parity.acquire.cta.shared::cta.b64 p, [%1], %2;\n\t" \
      "selp.b32 %0, 1, 0, p;\n\t}"                                            \
      : "=r"(_done) : "r"(_mbar), "r"(_par) : "memory");                      \
  if (!_done) {                                                               \
    asm volatile(                                                             \
        "{\n\t.reg .pred P1;\n\t"                                             \
        "WAIT_LOOP_%=:\n\t"                                                   \
        "mbarrier.try_wait.parity.acquire.cta.shared::cta.b64 P1, [%0], %1, 0x989680;\n\t" \
        "@P1 bra.uni WAIT_DONE_%=;\n\t"                                       \
        "bra.uni WAIT_LOOP_%=;\n\t"                                           \
        "WAIT_DONE_%=:\n\t}"                                                  \
        :: "r"(_mbar), "r"(_par) : "memory");                                 \
  }                                                                           \
} while (0)

__device__ __forceinline__ void pack_hilo(float p0, float p1, uint32_t& hi,
                                          uint32_t& lo) {
  __nv_bfloat162 h = __floats2bfloat162_rn(p0, p1);
  float r0 = p0 - __bfloat162float(h.x);
  float r1 = p1 - __bfloat162float(h.y);
  __nv_bfloat162 l = __floats2bfloat162_rn(r0, r1);
  hi = *reinterpret_cast<uint32_t*>(&h);
  lo = *reinterpret_cast<uint32_t*>(&l);
}

// ---------------------------------------------------------------------------
// fp32 [M,1024] row-major -> packed GEMM tiles (64B rows, seg^=((r>>1)&3)).
// ---------------------------------------------------------------------------
__global__ void cvt_pack_gemm(const float* __restrict__ x,
                              __nv_bfloat16* __restrict__ ph,
                              __nv_bfloat16* __restrict__ pl, int n) {
  int i = blockIdx.x * blockDim.x + threadIdx.x;
  if (i * 8 >= n) return;
  const float* src = x + (size_t)i * 8;
  float4 a = *(const float4*)src;
  float4 b = *(const float4*)(src + 4);
  uint32_t h0, h1, h2, h3, l0, l1, l2, l3;
  pack_hilo(a.x, a.y, h0, l0);
  pack_hilo(a.z, a.w, h1, l1);
  pack_hilo(b.x, b.y, h2, l2);
  pack_hilo(b.z, b.w, h3, l3);
  int m = (i * 8) >> 10, k = (i * 8) & 1023;
  int r = m & 127, mb = m >> 7, kc = k >> 5, seg = (k >> 3) & 3;
  size_t t = ((size_t)mb * 32 + kc) * 4096 + r * 32 +
             ((seg ^ ((r >> 1) & 3)) << 3);
  *(uint4*)(ph + t) = make_uint4(h0, h1, h2, h3);
  *(uint4*)(pl + t) = make_uint4(l0, l1, l2, l3);
}

__global__ void wpack4(const float* __restrict__ w0, const float* __restrict__ w1,
                       const float* __restrict__ w2, const float* __restrict__ w3,
                       __nv_bfloat16* __restrict__ ph,
                       __nv_bfloat16* __restrict__ pl) {
  int i = blockIdx.x * blockDim.x + threadIdx.x;
  int w = i >> 17, li = i & 131071;
  const float* src = (w == 0 ? w0 : w == 1 ? w1 : w == 2 ? w2 : w3) +
                     (size_t)li * 8;
  float4 a = *(const float4*)src;
  float4 b = *(const float4*)(src + 4);
  uint32_t h0, h1, h2, h3, l0, l1, l2, l3;
  pack_hilo(a.x, a.y, h0, l0);
  pack_hilo(a.z, a.w, h1, l1);
  pack_hilo(b.x, b.y, h2, l2);
  pack_hilo(b.z, b.w, h3, l3);
  int e = li * 8;
  int m = e >> 10, k = e & 1023;
  int r = m & 127, mb = m >> 7, kc = k >> 5, seg = (k >> 3) & 3;
  size_t t = (size_t)w * D_MODEL * D_MODEL +
             ((size_t)mb * 32 + kc) * 4096 + r * 32 +
             ((seg ^ ((r >> 1) & 3)) << 3);
  *(uint4*)(ph + t) = make_uint4(h0, h1, h2, h3);
  *(uint4*)(pl + t) = make_uint4(l0, l1, l2, l3);
}

// ---------------------------------------------------------------------------
// bf16x3 NT GEMM, 3-stage bulk-DMA pipeline with full/empty mbarriers
// (no per-chunk __syncthreads; warps free-run with <=1-chunk skew).
// ---------------------------------------------------------------------------
#define GS_TILE  8192
#define GS_STAGE 32768
#define GS_FULL  98304           // full[s]  = GS_FULL  + s*8
#define GS_EMPTY 98328           // empty[s] = GS_EMPTY + s*8
#define GS_SMEM  98432

template <int MODE>
__global__ __launch_bounds__(256, 2)
void gemm_bulk_t(const __nv_bfloat16* __restrict__ Ah,
                 const __nv_bfloat16* __restrict__ Al,
                 const __nv_bfloat16* __restrict__ Bh,
                 const __nv_bfloat16* __restrict__ Bl,
                 float* __restrict__ C,
                 __nv_bfloat16* __restrict__ Ph,
                 __nv_bfloat16* __restrict__ Pl, int M, int N, int K) {
  extern __shared__ __align__(128) char sm[];
  const uint32_t sb = smem_u32(sm);
  const int tid = threadIdx.x, lane = tid & 31, warp = tid >> 5;
  const int wm = (warp & 3) * 32;
  const int wn = (warp >> 2) * 64;
  const int bm = blockIdx.y * 128;
  const int bn = blockIdx.x * 128;
  const int nch = K >> 5;
  const int mb = bm >> 7, nb = bn >> 7;

  float acc[2][8][4];
#pragma unroll
  for (int mi = 0; mi < 2; mi++)
#pragma unroll
    for (int nj = 0; nj < 8; nj++)
#pragma unroll
      for (int q = 0; q < 4; q++) acc[mi][nj][q] = 0.0f;

  if (tid == 0) {
#pragma unroll
    for (int s = 0; s < 3; s++) {
      MBARRIER_INIT(sb + GS_FULL + s * 8, 1);
      MBARRIER_INIT(sb + GS_EMPTY + s * 8, 8);
    }
  }
  __syncthreads();

#define G_BULK(c_, s_) do {                                                   \
    uint32_t fb_ = sb + GS_FULL + (s_) * 8;                                   \
    MBARRIER_EXPECT_TX(fb_, 32768u);                                          \
    uint32_t d_ = sb + (uint32_t)(s_) * GS_STAGE;                             \
    bulk_g2s(d_,             Ah + ((size_t)(mb * nch + (c_))) * 4096, 8192u, fb_); \
    bulk_g2s(d_ + GS_TILE,   Al + ((size_t)(mb * nch + (c_))) * 4096, 8192u, fb_); \
    bulk_g2s(d_ + 2*GS_TILE, Bh + ((size_t)(nb * nch + (c_))) * 4096, 8192u, fb_); \
    bulk_g2s(d_ + 3*GS_TILE, Bl + ((size_t)(nb * nch + (c_))) * 4096, 8192u, fb_); \
  } while (0)

  if (tid == 0) {
    G_BULK(0, 0);
    G_BULK(1, 1);
  }

  const int ar = lane & 15;
  const int ac = ((lane >> 4) & 1) * 8;
  const int nof = ((lane >> 4) & 1) * 8 + (lane & 7);
  const int kof2 = ((lane >> 3) & 1) * 8;

  for (int c = 0; c < nch; c++) {
    const int cur = c % 3;
    const int cp = c + 2;
    if (cp < nch && tid == 0) {
      const int sp = cp % 3;
      if (cp >= 3)
        MBARRIER_WAIT_PARITY(sb + GS_EMPTY + sp * 8, ((cp / 3) - 1) & 1);
      G_BULK(cp, sp);
    }
    MBARRIER_WAIT_PARITY(sb + GS_FULL + cur * 8, (c / 3) & 1);

    const uint32_t st = sb + (uint32_t)cur * GS_STAGE;
#pragma unroll
    for (int ks = 0; ks < 2; ks++) {
      const int k0 = ks * 16;
      uint32_t afh[2][4], afl[2][4];
#pragma unroll
      for (int mi = 0; mi < 2; mi++) {
        int r = wm + mi * 16 + ar;
        int seg = (k0 + ac) >> 3;
        uint32_t ad = st + (uint32_t)(r * 64 + ((seg ^ ((r >> 1) & 3)) << 4));
        ldsm4(afh[mi], ad);
        ldsm4(afl[mi], ad + GS_TILE);
      }
#pragma unroll
      for (int ni = 0; ni < 4; ni++) {
        int rb = wn + ni * 16 + nof;
        int segb = (k0 + kof2) >> 3;
        uint32_t bd = st + 2 * GS_TILE +
                      (uint32_t)(rb * 64 + ((segb ^ ((rb >> 1) & 3)) << 4));
        uint32_t bh[4], bl[4];
        ldsm4(bh, bd);
        ldsm4(bl, bd + GS_TILE);
#pragma unroll
        for (int mi = 0; mi < 2; mi++)
#pragma unroll
          for (int hh = 0; hh < 2; hh++) {
            int nj = ni * 2 + hh;
            mma16816(acc[mi][nj], afh[mi], &bh[2 * hh]);
            mma16816(acc[mi][nj], afh[mi], &bl[2 * hh]);
            mma16816(acc[mi][nj], afl[mi], &bh[2 * hh]);
          }
      }
    }
    if (lane == 0) MBARRIER_ARRIVE(sb + GS_EMPTY + cur * 8);
  }

  // ---- epilogue ----
  const int crow = lane >> 2;
  const int ccol = (lane & 3) * 2;
#pragma unroll
  for (int mi = 0; mi < 2; mi++)
#pragma unroll
    for (int nj = 0; nj < 8; nj++) {
      int m0 = bm + wm + mi * 16 + crow;
      int cc = bn + wn + nj * 8 + ccol;
      if (MODE == 0) {
        *(float2*)(C + (size_t)m0 * N + cc) =
            make_float2(acc[mi][nj][0], acc[mi][nj][1]);
        *(float2*)(C + (size_t)(m0 + 8) * N + cc) =
            make_float2(acc[mi][nj][2], acc[mi][nj][3]);
      } else {
#pragma unroll
        for (int half = 0; half < 2; half++) {
          int m = m0 + half * 8;
          float v0 = acc[mi][nj][half * 2], v1 = acc[mi][nj][half * 2 + 1];
          size_t t;
          if (MODE == 1) {
            int b = m >> 11, q = m & 2047;
            int h = cc >> 6, dd = cc & 63;
            t = ((size_t)(b * 16 + h) * 16 + (q >> 7)) * 8192 +
                (size_t)(q & 127) * 64 + (((dd >> 3) ^ (q & 7)) << 3) + (dd & 7);
          } else if (MODE == 2) {
            int b = m >> 12, s = m & 4095;
            int h = cc >> 6, dd = cc & 63;
            t = ((size_t)(b * 16 + h) * 64 + (s >> 6)) * 4096 +
                (size_t)(s & 63) * 64 + (((dd >> 3) ^ (s & 7)) << 3) + (dd & 7);
          } else {
            int h = m >> 6, dr = m & 63;
            int b = cc >> 12, s = cc & 4095;
            t = ((size_t)(b * 16 + h) * 64 + (s >> 6)) * 4096 +
                (size_t)dr * 64 + ((((s >> 3) & 7) ^ (dr & 7)) << 3) + (s & 7);
          }
          uint32_t hi, lo;
          pack_hilo(v0, v1, hi, lo);
          *(uint32_t*)(Ph + t) = hi;
          *(uint32_t*)(Pl + t) = lo;
        }
      }
    }
}

// ---------------------------------------------------------------------------
// HMMA flash attention, 3-stage bulk-DMA K/V pipeline (stage 2 reuses the Q
// staging region after Q is consumed), full/empty mbarriers, no per-tile
// __syncthreads. bf16x3 QK^T and PV, P register-resident.
// ---------------------------------------------------------------------------
#define FS_TILE  8192
#define FS_STAGE 32768
#define FS_QOFF  65536           // Q staged in stage-2 region
#define FS_FULL  98304
#define FS_EMPTY 98328
#define FS_SMEM  98432

__global__ __launch_bounds__(256)
void flash_bulk(const __nv_bfloat16* __restrict__ qfh,
                const __nv_bfloat16* __restrict__ qfl,
                const __nv_bfloat16* __restrict__ kfh,
                const __nv_bfloat16* __restrict__ kfl,
                const __nv_bfloat16* __restrict__ vth,
                const __nv_bfloat16* __restrict__ vtl,
                const float* __restrict__ imp,
                __nv_bfloat16* __restrict__ Yh,
                __nv_bfloat16* __restrict__ Yl) {
  extern __shared__ __align__(128) char fsm[];
  const uint32_t sb = smem_u32(fsm);
  const int b = blockIdx.z, h = blockIdx.y, qb = blockIdx.x;
  const int q0 = qb * 128;
  const int tid = threadIdx.x, lane = tid & 31, warp = tid >> 5;
  const int wm = warp * 16;

  if (tid == 0) {
#pragma unroll
    for (int s = 0; s < 3; s++) {
      MBARRIER_INIT(sb + FS_FULL + s * 8, 1);
      MBARRIER_INIT(sb + FS_EMPTY + s * 8, 8);
    }
  }
  {
    const __nv_bfloat16* qsrc = qfh + ((size_t)(b * 16 + h) * 16 + qb) * 8192;
    const __nv_bfloat16* qsrc2 = qfl + ((size_t)(b * 16 + h) * 16 + qb) * 8192;
#pragma unroll
    for (int j = 0; j < 4; j++) {
      int idx = tid + j * 256;
      cp16(sb + FS_QOFF + idx * 16, qsrc + idx * 8);
      cp16(sb + FS_QOFF + 16384 + idx * 16, qsrc2 + idx * 8);
    }
  }
  CP_COMMIT();
  __syncthreads();              // mbar init visible

  const __nv_bfloat16* Kb = kfh + ((size_t)(b * 16 + h) * 64) * 4096;
  const __nv_bfloat16* Kb2 = kfl + ((size_t)(b * 16 + h) * 64) * 4096;
  const __nv_bfloat16* Vb = vth + ((size_t)(b * 16 + h) * 64) * 4096;
  const __nv_bfloat16* Vb2 = vtl + ((size_t)(b * 16 + h) * 64) * 4096;

#define F_BULK(t_, s_) do {                                                   \
    uint32_t fb_ = sb + FS_FULL + (s_) * 8;                                   \
    MBARRIER_EXPECT_TX(fb_, 32768u);                                          \
    uint32_t d_ = sb + (uint32_t)(s_) * FS_STAGE;                             \
    bulk_g2s(d_,             Kb  + (size_t)(t_) * 4096, 8192u, fb_);          \
    bulk_g2s(d_ + FS_TILE,   Kb2 + (size_t)(t_) * 4096, 8192u, fb_);          \
    bulk_g2s(d_ + 2*FS_TILE, Vb  + (size_t)(t_) * 4096, 8192u, fb_);          \
    bulk_g2s(d_ + 3*FS_TILE, Vb2 + (size_t)(t_) * 4096, 8192u, fb_);          \
  } while (0)

  if (tid == 0) {
    F_BULK(0, 0);               // stages 0 and 1 only — stage 2 holds Q
    F_BULK(1, 1);
  }

  const int ar = lane & 15;
  const int ac = ((lane >> 4) & 1) * 8;
  const int nof = ((lane >> 4) & 1) * 8 + (lane & 7);
  const int kof2 = ((lane >> 3) & 1) * 8;

  asm volatile("cp.async.wait_group 0;");
  __syncthreads();
  uint32_t qfa[4][4], qfb[4][4];
#pragma unroll
  for (int kc = 0; kc < 4; kc++) {
    int r = wm + ar;
    int seg = 2 * kc + (ac >> 3);
    uint32_t ad = sb + FS_QOFF + (uint32_t)(r * 128 + ((seg ^ (r & 7)) << 4));
    ldsm4(qfa[kc], ad);
    ldsm4(qfb[kc], ad + 16384);
  }
  __syncthreads();              // all warps consumed Q -> stage 2 reusable

  const int q2 = (lane & 3) * 2;
  float lg[4];
  lg[0] = logf(fmaxf(imp[b * NHEADS + (q2 & 15)], 1e-6f));
  lg[1] = logf(fmaxf(imp[b * NHEADS + ((q2 + 1) & 15)], 1e-6f));
  lg[2] = logf(fmaxf(imp[b * NHEADS + ((q2 + 8) & 15)], 1e-6f));
  lg[3] = logf(fmaxf(imp[b * NHEADS + ((q2 + 9) & 15)], 1e-6f));

  float m0 = -INFINITY, m1 = -INFINITY, l0 = 0.0f, l1 = 0.0f;
  float y[8][4];
#pragma unroll
  for (int nf = 0; nf < 8; nf++)
#pragma unroll
    for (int q = 0; q < 4; q++) y[nf][q] = 0.0f;

  const int NT = SKV / 64;
  for (int t = 0; t < NT; t++) {
    const int cur = t % 3;
    const int cp = t + 2;
    if (cp < NT && tid == 0) {
      const int sp = cp % 3;
      if (cp >= 3)
        MBARRIER_WAIT_PARITY(sb + FS_EMPTY + sp * 8, ((cp / 3) - 1) & 1);
      F_BULK(cp, sp);
    }
    MBARRIER_WAIT_PARITY(sb + FS_FULL + cur * 8, (t / 3) & 1);
    const uint32_t st = sb + (uint32_t)cur * FS_STAGE;

    float s[8][4];
#pragma unroll
    for (int nf = 0; nf < 8; nf++)
#pragma unroll
      for (int q = 0; q < 4; q++) s[nf][q] = 0.0f;
#pragma unroll
    for (int kc = 0; kc < 4; kc++) {
#pragma unroll
      for (int n2 = 0; n2 < 4; n2++) {
        int r = n2 * 16 + nof;
        int seg = 2 * kc + (kof2 >> 3);
        uint32_t bd = st + (uint32_t)(r * 128 + ((seg ^ (r & 7)) << 4));
        uint32_t bh[4], bl[4];
        ldsm4(bh, bd);
        ldsm4(bl, bd + FS_TILE);
#pragma unroll
        for (int hh = 0; hh < 2; hh++) {
          mma16816(s[n2 * 2 + hh], qfa[kc], &bh[2 * hh]);
          mma16816(s[n2 * 2 + hh], qfa[kc], &bl[2 * hh]);
          mma16816(s[n2 * 2 + hh], qfb[kc], &bh[2 * hh]);
        }
      }
    }

    float mt0 = -INFINITY, mt1 = -INFINITY;
#pragma unroll
    for (int nf = 0; nf < 8; nf++) {
      const int p = (nf & 1) * 2;
      s[nf][0] = s[nf][0] * 0.125f + lg[p];
      s[nf][1] = s[nf][1] * 0.125f + lg[p + 1];
      s[nf][2] = s[nf][2] * 0.125f + lg[p];
      s[nf][3] = s[nf][3] * 0.125f + lg[p + 1];
      mt0 = fmaxf(mt0, fmaxf(s[nf][0], s[nf][1]));
      mt1 = fmaxf(mt1, fmaxf(s[nf][2], s[nf][3]));
    }
    mt0 = fmaxf(mt0, __shfl_xor_sync(0xffffffffu, mt0, 1));
    mt0 = fmaxf(mt0, __shfl_xor_sync(0xffffffffu, mt0, 2));
    mt1 = fmaxf(mt1, __shfl_xor_sync(0xffffffffu, mt1, 1));
    mt1 = fmaxf(mt1, __shfl_xor_sync(0xffffffffu, mt1, 2));

    float mn0 = fmaxf(m0, mt0), mn1 = fmaxf(m1, mt1);
    float c0 = __expf(m0 - mn0), c1 = __expf(m1 - mn1);
    m0 = mn0; m1 = mn1;

    uint32_t ph[4][4], pl[4][4];
    float r0 = 0.0f, r1 = 0.0f;
#pragma unroll
    for (int nf = 0; nf < 8; nf++) {
      float p0 = __expf(s[nf][0] - m0);
      float p1 = __expf(s[nf][1] - m0);
      float p2 = __expf(s[nf][2] - m1);
      float p3 = __expf(s[nf][3] - m1);
      r0 += p0 + p1;
      r1 += p2 + p3;
      const int kc = nf >> 1, o = (nf & 1) * 2;
      pack_hilo(p0, p1, ph[kc][o], pl[kc][o]);
      pack_hilo(p2, p3, ph[kc][o + 1], pl[kc][o + 1]);
    }
    r0 += __shfl_xor_sync(0xffffffffu, r0, 1);
    r0 += __shfl_xor_sync(0xffffffffu, r0, 2);
    r1 += __shfl_xor_sync(0xffffffffu, r1, 1);
    r1 += __shfl_xor_sync(0xffffffffu, r1, 2);
    l0 = l0 * c0 + r0;
    l1 = l1 * c1 + r1;
#pragma unroll
    for (int nf = 0; nf < 8; nf++) {
      y[nf][0] *= c0; y[nf][1] *= c0;
      y[nf][2] *= c1; y[nf][3] *= c1;
    }

#pragma unroll
    for (int kc = 0; kc < 4; kc++) {
#pragma unroll
      for (int n2 = 0; n2 < 4; n2++) {
        int r = n2 * 16 + nof;
        int seg = 2 * kc + (kof2 >> 3);
        uint32_t bd = st + 2 * FS_TILE +
                      (uint32_t)(r * 128 + ((seg ^ (r & 7)) << 4));
        uint32_t vh[4], vl[4];
        ldsm4(vh, bd);
        ldsm4(vl, bd + FS_TILE);
#pragma unroll
        for (int hh = 0; hh < 2; hh++) {
          mma16816(y[n2 * 2 + hh], ph[kc], &vh[2 * hh]);
          mma16816(y[n2 * 2 + hh], ph[kc], &vl[2 * hh]);
          mma16816(y[n2 * 2 + hh], pl[kc], &vh[2 * hh]);
        }
      }
    }
    if (lane == 0) MBARRIER_ARRIVE(sb + FS_EMPTY + cur * 8);
  }

  // ---- epilogue: write Y as GEMM-A packed hi/lo tiles ----
  const float i0 = 1.0f / l0, i1 = 1.0f / l1;
  const int row0 = q0 + wm + (lane >> 2);
#pragma unroll
  for (int nf = 0; nf < 8; nf++) {
    int k = h * HDIM + 8 * nf + q2;
    int kc = k >> 5, seg0 = (k >> 3) & 3, klow = k & 7;
#pragma unroll
    for (int half = 0; half < 2; half++) {
      int m = b * TQ + row0 + half * 8;
      float v0 = y[nf][half * 2] * (half ? i1 : i0);
      float v1 = y[nf][half * 2 + 1] * (half ? i1 : i0);
      int r = m & 127, mb2 = m >> 7;
      size_t t = ((size_t)mb2 * 32 + kc) * 4096 + (size_t)r * 32 +
                 ((seg0 ^ ((r >> 1) & 3)) << 3) + klow;
      uint32_t hi, lo;
      pack_hilo(v0, v1, hi, lo);
      *(uint32_t*)(Yh + t) = hi;
      *(uint32_t*)(Yl + t) = lo;
    }
  }
}

// ---------------------------------------------------------------------------
extern "C" void kernel_launch(void* const* d_in, const int* in_sizes, int n_in,
                              void* d_out, int out_size) {
  const float* query     = (const float*)d_in[0];
  const float* key_value = (const float*)d_in[1];
  const float* imp       = (const float*)d_in[2];
  const float* Wq        = (const float*)d_in[3];
  const float* Wk        = (const float*)d_in[4];
  const float* Wv        = (const float*)d_in[5];
  const float* Wo        = (const float*)d_in[6];
  float* out = (float*)d_out;

  __nv_bfloat16 *qh, *ql, *kvh, *kvl, *yh, *yl, *wh, *wl, *kfh, *kfl, *vth, *vtl;
  cudaGetSymbolAddress((void**)&qh, g_qh);
  cudaGetSymbolAddress((void**)&ql, g_ql);
  cudaGetSymbolAddress((void**)&kvh, g_kvh);
  cudaGetSymbolAddress((void**)&kvl, g_kvl);
  cudaGetSymbolAddress((void**)&yh, g_yh);
  cudaGetSymbolAddress((void**)&yl, g_yl);
  cudaGetSymbolAddress((void**)&wh, g_wh);
  cudaGetSymbolAddress((void**)&wl, g_wl);
  cudaGetSymbolAddress((void**)&kfh, g_kfh);
  cudaGetSymbolAddress((void**)&kfl, g_kfl);
  cudaGetSymbolAddress((void**)&vth, g_vth);
  cudaGetSymbolAddress((void**)&vtl, g_vtl);
  const size_t WSZ = (size_t)D_MODEL * D_MODEL;

  cudaFuncSetAttribute(gemm_bulk_t<0>,
                       cudaFuncAttributeMaxDynamicSharedMemorySize, GS_SMEM);
  cudaFuncSetAttribute(gemm_bulk_t<1>,
                       cudaFuncAttributeMaxDynamicSharedMemorySize, GS_SMEM);
  cudaFuncSetAttribute(gemm_bulk_t<2>,
                       cudaFuncAttributeMaxDynamicSharedMemorySize, GS_SMEM);
  cudaFuncSetAttribute(gemm_bulk_t<3>,
                       cudaFuncAttributeMaxDynamicSharedMemorySize, GS_SMEM);
  cudaFuncSetAttribute(flash_bulk,
                       cudaFuncAttributeMaxDynamicSharedMemorySize, FS_SMEM);

  const int NQ = BATCH * TQ * D_MODEL;
  const int NKV = BATCH * SKV * D_MODEL;

  cvt_pack_gemm<<<NQ / 2048, 256>>>(query, qh, ql, NQ);
  cvt_pack_gemm<<<NKV / 2048, 256>>>(key_value, kvh, kvl, NKV);
  wpack4<<<2048, 256>>>(Wq, Wk, Wv, Wo, wh, wl);

  gemm_bulk_t<1><<<dim3(8, 32), 256, GS_SMEM>>>(
      qh, ql, wh + 0 * WSZ, wl + 0 * WSZ, nullptr, yh, yl,
      BATCH * TQ, D_MODEL, D_MODEL);
  gemm_bulk_t<2><<<dim3(8, 64), 256, GS_SMEM>>>(
      kvh, kvl, wh + 1 * WSZ, wl + 1 * WSZ, nullptr, kfh, kfl,
      BATCH * SKV, D_MODEL, D_MODEL);
  gemm_bulk_t<3><<<dim3(64, 8), 256, GS_SMEM>>>(
      wh + 2 * WSZ, wl + 2 * WSZ, kvh, kvl, nullptr, vth, vtl,
      D_MODEL, BATCH * SKV, D_MODEL);

  flash_bulk<<<dim3(TQ / 128, NHEADS, BATCH), 256, FS_SMEM>>>(
      yh, yl, kfh, kfl, vth, vtl, imp, qh, ql);

  gemm_bulk_t<0><<<dim3(8, 32), 256, GS_SMEM>>>(
      qh, ql, wh + 3 * WSZ, wl + 3 * WSZ, out, nullptr, nullptr,
      BATCH * TQ, D_MODEL, D_MODEL);
}

// round 9
// speedup vs baseline: 3.5454x; 1.0324x over previous
#include <cuda_runtime.h>
#include <cuda_bf16.h>
#include <cstdint>
#include <math.h>

#define D_MODEL 1024
#define BATCH   2
#define TQ      2048
#define SKV     4096
#define NHEADS  16
#define HDIM    64

// ---------------- scratch (no cudaMalloc allowed) ----------------
__device__ __align__(256) __nv_bfloat16 g_qh[(size_t)BATCH * TQ  * D_MODEL];
__device__ __align__(256) __nv_bfloat16 g_ql[(size_t)BATCH * TQ  * D_MODEL];
__device__ __align__(256) __nv_bfloat16 g_kvh[(size_t)BATCH * SKV * D_MODEL];
__device__ __align__(256) __nv_bfloat16 g_kvl[(size_t)BATCH * SKV * D_MODEL];
__device__ __align__(256) __nv_bfloat16 g_yh[(size_t)BATCH * TQ  * D_MODEL];
__device__ __align__(256) __nv_bfloat16 g_yl[(size_t)BATCH * TQ  * D_MODEL];
__device__ __align__(256) __nv_bfloat16 g_wh[4][(size_t)D_MODEL * D_MODEL];
__device__ __align__(256) __nv_bfloat16 g_wl[4][(size_t)D_MODEL * D_MODEL];
__device__ __align__(256) __nv_bfloat16 g_kfh[(size_t)BATCH * SKV * D_MODEL];
__device__ __align__(256) __nv_bfloat16 g_kfl[(size_t)BATCH * SKV * D_MODEL];
__device__ __align__(256) __nv_bfloat16 g_vth[(size_t)BATCH * NHEADS * HDIM * SKV];
__device__ __align__(256) __nv_bfloat16 g_vtl[(size_t)BATCH * NHEADS * HDIM * SKV];

// ---------------- primitives ----------------
__device__ __forceinline__ uint32_t smem_u32(const void* p) {
  uint32_t a;
  asm("{ .reg .u64 t; cvta.to.shared.u64 t, %1; cvt.u32.u64 %0, t; }"
      : "=r"(a) : "l"(p));
  return a;
}
__device__ __forceinline__ void ldsm4(uint32_t* r, uint32_t a) {
  asm volatile("ldmatrix.sync.aligned.m8n8.x4.shared.b16 {%0,%1,%2,%3}, [%4];"
               : "=r"(r[0]), "=r"(r[1]), "=r"(r[2]), "=r"(r[3]) : "r"(a));
}
__device__ __forceinline__ void mma16816(float* d, const uint32_t* a,
                                         const uint32_t* b) {
  asm volatile(
      "mma.sync.aligned.m16n8k16.row.col.f32.bf16.bf16.f32 "
      "{%0,%1,%2,%3}, {%4,%5,%6,%7}, {%8,%9}, {%0,%1,%2,%3};"
      : "+f"(d[0]), "+f"(d[1]), "+f"(d[2]), "+f"(d[3])
      : "r"(a[0]), "r"(a[1]), "r"(a[2]), "r"(a[3]), "r"(b[0]), "r"(b[1]));
}
__device__ __forceinline__ void cp16(uint32_t dst, const void* src) {
  asm volatile("cp.async.cg.shared.global [%0], [%1], 16;" :: "r"(dst), "l"(src));
}
#define CP_COMMIT() asm volatile("cp.async.commit_group;")

__device__ __forceinline__ void bulk_g2s(uint32_t dst, const void* src,
                                         uint32_t bytes, uint32_t mbar) {
  asm volatile(
      "cp.async.bulk.shared::cluster.global.mbarrier::complete_tx::bytes "
      "[%0], [%1], %2, [%3];"
      :: "r"(dst), "l"(src), "r"(bytes), "r"(mbar) : "memory");
}
#define MBARRIER_INIT(mbar, count)                                            \
  asm volatile("mbarrier.init.shared.b64 [%0], %1;"                           \
               :: "r"((uint32_t)(mbar)), "r"((uint32_t)(count)) : "memory")
#define MBARRIER_EXPECT_TX(mbar, tx)                                          \
  asm volatile("mbarrier.arrive.expect_tx.shared.b64 _, [%0], %1;"            \
               :: "r"((uint32_t)(mbar)), "r"((uint32_t)(tx)) : "memory")
#define MBARRIER_ARRIVE(mbar)                                                 \
  asm volatile("mbarrier.arrive.shared.b64 _, [%0];"                          \
               :: "r"((uint32_t)(mbar)) : "memory")
#define MBARRIER_WAIT_PARITY(mbar_addr, phase_parity) do {                    \
  uint32_t _mbar = (uint32_t)(mbar_addr);                                     \
  uint32_t _par = (uint32_t)(phase_parity);                                   \
  uint32_t _done;                                                             \
  asm volatile(                                                               \
      "{\n\t.reg .pred p;\n\t"                                                \
      "mbarrier.try_wait.parity.acquire.cta.shared::cta.b64 p, [%1], %2;\n\t" \
      "selp.b32 %0, 1, 0, p;\n\t}"                                            \
      : "=r"(_done) : "r"(_mbar), "r"(_par) : "memory");                      \
  if (!_done) {                                                               \
    asm volatile(                                                             \
        "{\n\t.reg .pred P1;\n\t"                                             \
        "WAIT_LOOP_%=:\n\t"                                                   \
        "mbarrier.try_wait.parity.acquire.cta.shared::cta.b64 P1, [%0], %1, 0x989680;\n\t" \
        "@P1 bra.uni WAIT_DONE_%=;\n\t"                                       \
        "bra.uni WAIT_LOOP_%=;\n\t"                                           \
        "WAIT_DONE_%=:\n\t}"                                                  \
        :: "r"(_mbar), "r"(_par) : "memory");                                 \
  }                                                                           \
} while (0)

__device__ __forceinline__ void pack_hilo(float p0, float p1, uint32_t& hi,
                                          uint32_t& lo) {
  __nv_bfloat162 h = __floats2bfloat162_rn(p0, p1);
  float r0 = p0 - __bfloat162float(h.x);
  float r1 = p1 - __bfloat162float(h.y);
  __nv_bfloat162 l = __floats2bfloat162_rn(r0, r1);
  hi = *reinterpret_cast<uint32_t*>(&h);
  lo = *reinterpret_cast<uint32_t*>(&l);
}

// ---------------------------------------------------------------------------
// Fused pack: query + key_value + 4 weights, all in one launch.
// GEMM tile layout: [mb][kc][128x32 halves], 64B rows, seg^=((r>>1)&3).
// ---------------------------------------------------------------------------
#define NQ8  (BATCH * TQ * D_MODEL / 8)    // 524288
#define NKV8 (BATCH * SKV * D_MODEL / 8)   // 1048576
#define NW8  (D_MODEL * D_MODEL / 8)       // 131072

__global__ void pack_all(const float* __restrict__ query,
                         const float* __restrict__ key_value,
                         const float* __restrict__ w0,
                         const float* __restrict__ w1,
                         const float* __restrict__ w2,
                         const float* __restrict__ w3,
                         __nv_bfloat16* __restrict__ qh,
                         __nv_bfloat16* __restrict__ ql,
                         __nv_bfloat16* __restrict__ kvh,
                         __nv_bfloat16* __restrict__ kvl,
                         __nv_bfloat16* __restrict__ wph,
                         __nv_bfloat16* __restrict__ wpl) {
  int id = blockIdx.x * blockDim.x + threadIdx.x;
  const float* src;
  __nv_bfloat16 *dh, *dl;
  size_t base;
  int e;
  if (id < NQ8) {
    src = query + (size_t)id * 8;
    dh = qh; dl = ql; base = 0; e = id * 8;
  } else if (id < NQ8 + NKV8) {
    int li = id - NQ8;
    src = key_value + (size_t)li * 8;
    dh = kvh; dl = kvl; base = 0; e = li * 8;
  } else {
    int li = id - NQ8 - NKV8;          // 0 .. 4*NW8-1
    int w = li >> 17, wi = li & (NW8 - 1);
    src = (w == 0 ? w0 : w == 1 ? w1 : w == 2 ? w2 : w3) + (size_t)wi * 8;
    dh = wph; dl = wpl; base = (size_t)w * D_MODEL * D_MODEL; e = wi * 8;
  }
  float4 a = *(const float4*)src;
  float4 b = *(const float4*)(src + 4);
  uint32_t h0, h1, h2, h3, l0, l1, l2, l3;
  pack_hilo(a.x, a.y, h0, l0);
  pack_hilo(a.z, a.w, h1, l1);
  pack_hilo(b.x, b.y, h2, l2);
  pack_hilo(b.z, b.w, h3, l3);
  int m = e >> 10, k = e & 1023;
  int r = m & 127, mb = m >> 7, kc = k >> 5, seg = (k >> 3) & 3;
  size_t t = base + ((size_t)mb * 32 + kc) * 4096 + r * 32 +
             ((seg ^ ((r >> 1) & 3)) << 3);
  *(uint4*)(dh + t) = make_uint4(h0, h1, h2, h3);
  *(uint4*)(dl + t) = make_uint4(l0, l1, l2, l3);
}

// ---------------------------------------------------------------------------
// GEMM core shared by fused-projection and O-projection kernels.
// bf16x3 NT GEMM, 3-stage bulk-DMA pipeline, full/empty mbarriers.
// K fixed at 1024 (NCH=32 chunks).
// ---------------------------------------------------------------------------
#define NCH      32
#define GS_TILE  8192
#define GS_STAGE 32768
#define GS_FULL  98304
#define GS_EMPTY 98328
#define GS_SMEM  98432

// Mainloop: accumulates into acc; operands are packed-tile base pointers.
__device__ __forceinline__ void gemm_mainloop(
    const __nv_bfloat16* Ah, const __nv_bfloat16* Al,
    const __nv_bfloat16* Bh, const __nv_bfloat16* Bl,
    int mb, int nb, uint32_t sb, int tid, int lane, int warp,
    float acc[2][8][4]) {
  const int wm = (warp & 3) * 32;
  const int wn = (warp >> 2) * 64;

  if (tid == 0) {
#pragma unroll
    for (int s = 0; s < 3; s++) {
      MBARRIER_INIT(sb + GS_FULL + s * 8, 1);
      MBARRIER_INIT(sb + GS_EMPTY + s * 8, 8);
    }
  }
  __syncthreads();

#define G_BULK(c_, s_) do {                                                   \
    uint32_t fb_ = sb + GS_FULL + (s_) * 8;                                   \
    MBARRIER_EXPECT_TX(fb_, 32768u);                                          \
    uint32_t d_ = sb + (uint32_t)(s_) * GS_STAGE;                             \
    bulk_g2s(d_,             Ah + ((size_t)(mb * NCH + (c_))) * 4096, 8192u, fb_); \
    bulk_g2s(d_ + GS_TILE,   Al + ((size_t)(mb * NCH + (c_))) * 4096, 8192u, fb_); \
    bulk_g2s(d_ + 2*GS_TILE, Bh + ((size_t)(nb * NCH + (c_))) * 4096, 8192u, fb_); \
    bulk_g2s(d_ + 3*GS_TILE, Bl + ((size_t)(nb * NCH + (c_))) * 4096, 8192u, fb_); \
  } while (0)

  if (tid == 0) {
    G_BULK(0, 0);
    G_BULK(1, 1);
  }

  const int ar = lane & 15;
  const int ac = ((lane >> 4) & 1) * 8;
  const int nof = ((lane >> 4) & 1) * 8 + (lane & 7);
  const int kof2 = ((lane >> 3) & 1) * 8;

  for (int c = 0; c < NCH; c++) {
    const int cur = c % 3;
    const int cp = c + 2;
    if (cp < NCH && tid == 0) {
      const int sp = cp % 3;
      if (cp >= 3)
        MBARRIER_WAIT_PARITY(sb + GS_EMPTY + sp * 8, ((cp / 3) - 1) & 1);
      G_BULK(cp, sp);
    }
    MBARRIER_WAIT_PARITY(sb + GS_FULL + cur * 8, (c / 3) & 1);

    const uint32_t st = sb + (uint32_t)cur * GS_STAGE;
#pragma unroll
    for (int ks = 0; ks < 2; ks++) {
      const int k0 = ks * 16;
      uint32_t afh[2][4], afl[2][4];
#pragma unroll
      for (int mi = 0; mi < 2; mi++) {
        int r = wm + mi * 16 + ar;
        int seg = (k0 + ac) >> 3;
        uint32_t ad = st + (uint32_t)(r * 64 + ((seg ^ ((r >> 1) & 3)) << 4));
        ldsm4(afh[mi], ad);
        ldsm4(afl[mi], ad + GS_TILE);
      }
#pragma unroll
      for (int ni = 0; ni < 4; ni++) {
        int rb = wn + ni * 16 + nof;
        int segb = (k0 + kof2) >> 3;
        uint32_t bd = st + 2 * GS_TILE +
                      (uint32_t)(rb * 64 + ((segb ^ ((rb >> 1) & 3)) << 4));
        uint32_t bh[4], bl[4];
        ldsm4(bh, bd);
        ldsm4(bl, bd + GS_TILE);
#pragma unroll
        for (int mi = 0; mi < 2; mi++)
#pragma unroll
          for (int hh = 0; hh < 2; hh++) {
            int nj = ni * 2 + hh;
            mma16816(acc[mi][nj], afh[mi], &bh[2 * hh]);
            mma16816(acc[mi][nj], afh[mi], &bl[2 * hh]);
            mma16816(acc[mi][nj], afl[mi], &bh[2 * hh]);
          }
      }
    }
    if (lane == 0) MBARRIER_ARRIVE(sb + GS_EMPTY + cur * 8);
  }
#undef G_BULK
}

// ---------------------------------------------------------------------------
// Fused Q/K/V projection: 1280 CTAs, runtime mode decode.
//   id <  256 : Q-proj  (M=B*TQ,  bx=id&7,  by=id>>3)  -> flash-Q pack
//   id <  768 : K-proj  (M=B*SKV, bx=id&7,  by=id>>3)  -> flash-K pack
//   id >= 768 : V-proj  (transposed: A=Wv, B=kv; bx=id&63, by=id>>6)
// ---------------------------------------------------------------------------
__global__ __launch_bounds__(256, 2)
void proj_fused(const __nv_bfloat16* __restrict__ qh,
                const __nv_bfloat16* __restrict__ ql,
                const __nv_bfloat16* __restrict__ kvh,
                const __nv_bfloat16* __restrict__ kvl,
                const __nv_bfloat16* __restrict__ wph,
                const __nv_bfloat16* __restrict__ wpl,
                __nv_bfloat16* __restrict__ yh,
                __nv_bfloat16* __restrict__ yl,
                __nv_bfloat16* __restrict__ kfh,
                __nv_bfloat16* __restrict__ kfl,
                __nv_bfloat16* __restrict__ vth,
                __nv_bfloat16* __restrict__ vtl) {
  extern __shared__ __align__(128) char sm[];
  const uint32_t sb = smem_u32(sm);
  const int tid = threadIdx.x, lane = tid & 31, warp = tid >> 5;
  const size_t WSZ = (size_t)D_MODEL * D_MODEL;

  int id = blockIdx.x;
  int mode, bx, by;
  const __nv_bfloat16 *Ah, *Al, *Bh, *Bl;
  __nv_bfloat16 *Ph, *Pl;
  if (id < 256) {
    mode = 1; bx = id & 7; by = id >> 3;
    Ah = qh; Al = ql; Bh = wph; Bl = wpl; Ph = yh; Pl = yl;
  } else if (id < 768) {
    mode = 2; id -= 256; bx = id & 7; by = id >> 3;
    Ah = kvh; Al = kvl; Bh = wph + WSZ; Bl = wpl + WSZ; Ph = kfh; Pl = kfl;
  } else {
    mode = 3; id -= 768; bx = id & 63; by = id >> 6;
    Ah = wph + 2 * WSZ; Al = wpl + 2 * WSZ; Bh = kvh; Bl = kvl;
    Ph = vth; Pl = vtl;
  }
  const int bm = by * 128, bn = bx * 128;

  float acc[2][8][4];
#pragma unroll
  for (int mi = 0; mi < 2; mi++)
#pragma unroll
    for (int nj = 0; nj < 8; nj++)
#pragma unroll
      for (int q = 0; q < 4; q++) acc[mi][nj][q] = 0.0f;

  gemm_mainloop(Ah, Al, Bh, Bl, by, bx, sb, tid, lane, warp, acc);

  // ---- epilogue: pack into flash tile layouts ----
  const int wm = (warp & 3) * 32;
  const int wn = (warp >> 2) * 64;
  const int crow = lane >> 2;
  const int ccol = (lane & 3) * 2;
#pragma unroll
  for (int mi = 0; mi < 2; mi++)
#pragma unroll
    for (int nj = 0; nj < 8; nj++) {
      int m0 = bm + wm + mi * 16 + crow;
      int cc = bn + wn + nj * 8 + ccol;
#pragma unroll
      for (int half = 0; half < 2; half++) {
        int m = m0 + half * 8;
        float v0 = acc[mi][nj][half * 2], v1 = acc[mi][nj][half * 2 + 1];
        size_t t;
        if (mode == 1) {
          int b = m >> 11, q = m & 2047;
          int h = cc >> 6, dd = cc & 63;
          t = ((size_t)(b * 16 + h) * 16 + (q >> 7)) * 8192 +
              (size_t)(q & 127) * 64 + (((dd >> 3) ^ (q & 7)) << 3) + (dd & 7);
        } else if (mode == 2) {
          int b = m >> 12, s = m & 4095;
          int h = cc >> 6, dd = cc & 63;
          t = ((size_t)(b * 16 + h) * 64 + (s >> 6)) * 4096 +
              (size_t)(s & 63) * 64 + (((dd >> 3) ^ (s & 7)) << 3) + (dd & 7);
        } else {
          int h = m >> 6, dr = m & 63;
          int b = cc >> 12, s = cc & 4095;
          t = ((size_t)(b * 16 + h) * 64 + (s >> 6)) * 4096 +
              (size_t)dr * 64 + ((((s >> 3) & 7) ^ (dr & 7)) << 3) + (s & 7);
        }
        uint32_t hi, lo;
        pack_hilo(v0, v1, hi, lo);
        *(uint32_t*)(Ph + t) = hi;
        *(uint32_t*)(Pl + t) = lo;
      }
    }
}

// ---------------------------------------------------------------------------
// Output projection: fp32 C row-major (straight into d_out).
// ---------------------------------------------------------------------------
__global__ __launch_bounds__(256, 2)
void gemm_out(const __nv_bfloat16* __restrict__ Ah,
              const __nv_bfloat16* __restrict__ Al,
              const __nv_bfloat16* __restrict__ Bh,
              const __nv_bfloat16* __restrict__ Bl,
              float* __restrict__ C, int N) {
  extern __shared__ __align__(128) char sm[];
  const uint32_t sb = smem_u32(sm);
  const int tid = threadIdx.x, lane = tid & 31, warp = tid >> 5;
  const int bm = blockIdx.y * 128;
  const int bn = blockIdx.x * 128;

  float acc[2][8][4];
#pragma unroll
  for (int mi = 0; mi < 2; mi++)
#pragma unroll
    for (int nj = 0; nj < 8; nj++)
#pragma unroll
      for (int q = 0; q < 4; q++) acc[mi][nj][q] = 0.0f;

  gemm_mainloop(Ah, Al, Bh, Bl, blockIdx.y, blockIdx.x, sb, tid, lane, warp, acc);

  const int wm = (warp & 3) * 32;
  const int wn = (warp >> 2) * 64;
  const int crow = lane >> 2;
  const int ccol = (lane & 3) * 2;
#pragma unroll
  for (int mi = 0; mi < 2; mi++)
#pragma unroll
    for (int nj = 0; nj < 8; nj++) {
      int r0 = bm + wm + mi * 16 + crow;
      int cc = bn + wn + nj * 8 + ccol;
      *(float2*)(C + (size_t)r0 * N + cc) =
          make_float2(acc[mi][nj][0], acc[mi][nj][1]);
      *(float2*)(C + (size_t)(r0 + 8) * N + cc) =
          make_float2(acc[mi][nj][2], acc[mi][nj][3]);
    }
}

// ---------------------------------------------------------------------------
// HMMA flash attention (unchanged from round 8): 3-stage bulk-DMA K/V,
// full/empty mbarriers, bf16x3 QK^T and PV, P register-resident,
// epilogue writes Y as GEMM-A packed tiles.
// ---------------------------------------------------------------------------
#define FS_TILE  8192
#define FS_STAGE 32768
#define FS_QOFF  65536
#define FS_FULL  98304
#define FS_EMPTY 98328
#define FS_SMEM  98432

__global__ __launch_bounds__(256)
void flash_bulk(const __nv_bfloat16* __restrict__ qfh,
                const __nv_bfloat16* __restrict__ qfl,
                const __nv_bfloat16* __restrict__ kfh,
                const __nv_bfloat16* __restrict__ kfl,
                const __nv_bfloat16* __restrict__ vth,
                const __nv_bfloat16* __restrict__ vtl,
                const float* __restrict__ imp,
                __nv_bfloat16* __restrict__ Yh,
                __nv_bfloat16* __restrict__ Yl) {
  extern __shared__ __align__(128) char fsm[];
  const uint32_t sb = smem_u32(fsm);
  const int b = blockIdx.z, h = blockIdx.y, qb = blockIdx.x;
  const int q0 = qb * 128;
  const int tid = threadIdx.x, lane = tid & 31, warp = tid >> 5;
  const int wm = warp * 16;

  if (tid == 0) {
#pragma unroll
    for (int s = 0; s < 3; s++) {
      MBARRIER_INIT(sb + FS_FULL + s * 8, 1);
      MBARRIER_INIT(sb + FS_EMPTY + s * 8, 8);
    }
  }
  {
    const __nv_bfloat16* qsrc = qfh + ((size_t)(b * 16 + h) * 16 + qb) * 8192;
    const __nv_bfloat16* qsrc2 = qfl + ((size_t)(b * 16 + h) * 16 + qb) * 8192;
#pragma unroll
    for (int j = 0; j < 4; j++) {
      int idx = tid + j * 256;
      cp16(sb + FS_QOFF + idx * 16, qsrc + idx * 8);
      cp16(sb + FS_QOFF + 16384 + idx * 16, qsrc2 + idx * 8);
    }
  }
  CP_COMMIT();
  __syncthreads();

  const __nv_bfloat16* Kb = kfh + ((size_t)(b * 16 + h) * 64) * 4096;
  const __nv_bfloat16* Kb2 = kfl + ((size_t)(b * 16 + h) * 64) * 4096;
  const __nv_bfloat16* Vb = vth + ((size_t)(b * 16 + h) * 64) * 4096;
  const __nv_bfloat16* Vb2 = vtl + ((size_t)(b * 16 + h) * 64) * 4096;

#define F_BULK(t_, s_) do {                                                   \
    uint32_t fb_ = sb + FS_FULL + (s_) * 8;                                   \
    MBARRIER_EXPECT_TX(fb_, 32768u);                                          \
    uint32_t d_ = sb + (uint32_t)(s_) * FS_STAGE;                             \
    bulk_g2s(d_,             Kb  + (size_t)(t_) * 4096, 8192u, fb_);          \
    bulk_g2s(d_ + FS_TILE,   Kb2 + (size_t)(t_) * 4096, 8192u, fb_);          \
    bulk_g2s(d_ + 2*FS_TILE, Vb  + (size_t)(t_) * 4096, 8192u, fb_);          \
    bulk_g2s(d_ + 3*FS_TILE, Vb2 + (size_t)(t_) * 4096, 8192u, fb_);          \
  } while (0)

  if (tid == 0) {
    F_BULK(0, 0);
    F_BULK(1, 1);
  }

  const int ar = lane & 15;
  const int ac = ((lane >> 4) & 1) * 8;
  const int nof = ((lane >> 4) & 1) * 8 + (lane & 7);
  const int kof2 = ((lane >> 3) & 1) * 8;

  asm volatile("cp.async.wait_group 0;");
  __syncthreads();
  uint32_t qfa[4][4], qfb[4][4];
#pragma unroll
  for (int kc = 0; kc < 4; kc++) {
    int r = wm + ar;
    int seg = 2 * kc + (ac >> 3);
    uint32_t ad = sb + FS_QOFF + (uint32_t)(r * 128 + ((seg ^ (r & 7)) << 4));
    ldsm4(qfa[kc], ad);
    ldsm4(qfb[kc], ad + 16384);
  }
  __syncthreads();

  const int q2 = (lane & 3) * 2;
  float lg[4];
  lg[0] = logf(fmaxf(imp[b * NHEADS + (q2 & 15)], 1e-6f));
  lg[1] = logf(fmaxf(imp[b * NHEADS + ((q2 + 1) & 15)], 1e-6f));
  lg[2] = logf(fmaxf(imp[b * NHEADS + ((q2 + 8) & 15)], 1e-6f));
  lg[3] = logf(fmaxf(imp[b * NHEADS + ((q2 + 9) & 15)], 1e-6f));

  float m0 = -INFINITY, m1 = -INFINITY, l0 = 0.0f, l1 = 0.0f;
  float y[8][4];
#pragma unroll
  for (int nf = 0; nf < 8; nf++)
#pragma unroll
    for (int q = 0; q < 4; q++) y[nf][q] = 0.0f;

  const int NT = SKV / 64;
  for (int t = 0; t < NT; t++) {
    const int cur = t % 3;
    const int cp = t + 2;
    if (cp < NT && tid == 0) {
      const int sp = cp % 3;
      if (cp >= 3)
        MBARRIER_WAIT_PARITY(sb + FS_EMPTY + sp * 8, ((cp / 3) - 1) & 1);
      F_BULK(cp, sp);
    }
    MBARRIER_WAIT_PARITY(sb + FS_FULL + cur * 8, (t / 3) & 1);
    const uint32_t st = sb + (uint32_t)cur * FS_STAGE;

    float s[8][4];
#pragma unroll
    for (int nf = 0; nf < 8; nf++)
#pragma unroll
      for (int q = 0; q < 4; q++) s[nf][q] = 0.0f;
#pragma unroll
    for (int kc = 0; kc < 4; kc++) {
#pragma unroll
      for (int n2 = 0; n2 < 4; n2++) {
        int r = n2 * 16 + nof;
        int seg = 2 * kc + (kof2 >> 3);
        uint32_t bd = st + (uint32_t)(r * 128 + ((seg ^ (r & 7)) << 4));
        uint32_t bh[4], bl[4];
        ldsm4(bh, bd);
        ldsm4(bl, bd + FS_TILE);
#pragma unroll
        for (int hh = 0; hh < 2; hh++) {
          mma16816(s[n2 * 2 + hh], qfa[kc], &bh[2 * hh]);
          mma16816(s[n2 * 2 + hh], qfa[kc], &bl[2 * hh]);
          mma16816(s[n2 * 2 + hh], qfb[kc], &bh[2 * hh]);
        }
      }
    }

    float mt0 = -INFINITY, mt1 = -INFINITY;
#pragma unroll
    for (int nf = 0; nf < 8; nf++) {
      const int p = (nf & 1) * 2;
      s[nf][0] = s[nf][0] * 0.125f + lg[p];
      s[nf][1] = s[nf][1] * 0.125f + lg[p + 1];
      s[nf][2] = s[nf][2] * 0.125f + lg[p];
      s[nf][3] = s[nf][3] * 0.125f + lg[p + 1];
      mt0 = fmaxf(mt0, fmaxf(s[nf][0], s[nf][1]));
      mt1 = fmaxf(mt1, fmaxf(s[nf][2], s[nf][3]));
    }
    mt0 = fmaxf(mt0, __shfl_xor_sync(0xffffffffu, mt0, 1));
    mt0 = fmaxf(mt0, __shfl_xor_sync(0xffffffffu, mt0, 2));
    mt1 = fmaxf(mt1, __shfl_xor_sync(0xffffffffu, mt1, 1));
    mt1 = fmaxf(mt1, __shfl_xor_sync(0xffffffffu, mt1, 2));

    float mn0 = fmaxf(m0, mt0), mn1 = fmaxf(m1, mt1);
    float c0 = __expf(m0 - mn0), c1 = __expf(m1 - mn1);
    m0 = mn0; m1 = mn1;

    uint32_t ph[4][4], pl[4][4];
    float r0 = 0.0f, r1 = 0.0f;
#pragma unroll
    for (int nf = 0; nf < 8; nf++) {
      float p0 = __expf(s[nf][0] - m0);
      float p1 = __expf(s[nf][1] - m0);
      float p2 = __expf(s[nf][2] - m1);
      float p3 = __expf(s[nf][3] - m1);
      r0 += p0 + p1;
      r1 += p2 + p3;
      const int kc = nf >> 1, o = (nf & 1) * 2;
      pack_hilo(p0, p1, ph[kc][o], pl[kc][o]);
      pack_hilo(p2, p3, ph[kc][o + 1], pl[kc][o + 1]);
    }
    r0 += __shfl_xor_sync(0xffffffffu, r0, 1);
    r0 += __shfl_xor_sync(0xffffffffu, r0, 2);
    r1 += __shfl_xor_sync(0xffffffffu, r1, 1);
    r1 += __shfl_xor_sync(0xffffffffu, r1, 2);
    l0 = l0 * c0 + r0;
    l1 = l1 * c1 + r1;
#pragma unroll
    for (int nf = 0; nf < 8; nf++) {
      y[nf][0] *= c0; y[nf][1] *= c0;
      y[nf][2] *= c1; y[nf][3] *= c1;
    }

#pragma unroll
    for (int kc = 0; kc < 4; kc++) {
#pragma unroll
      for (int n2 = 0; n2 < 4; n2++) {
        int r = n2 * 16 + nof;
        int seg = 2 * kc + (kof2 >> 3);
        uint32_t bd = st + 2 * FS_TILE +
                      (uint32_t)(r * 128 + ((seg ^ (r & 7)) << 4));
        uint32_t vh[4], vl[4];
        ldsm4(vh, bd);
        ldsm4(vl, bd + FS_TILE);
#pragma unroll
        for (int hh = 0; hh < 2; hh++) {
          mma16816(y[n2 * 2 + hh], ph[kc], &vh[2 * hh]);
          mma16816(y[n2 * 2 + hh], ph[kc], &vl[2 * hh]);
          mma16816(y[n2 * 2 + hh], pl[kc], &vh[2 * hh]);
        }
      }
    }
    if (lane == 0) MBARRIER_ARRIVE(sb + FS_EMPTY + cur * 8);
  }

  const float i0 = 1.0f / l0, i1 = 1.0f / l1;
  const int row0 = q0 + wm + (lane >> 2);
#pragma unroll
  for (int nf = 0; nf < 8; nf++) {
    int k = h * HDIM + 8 * nf + q2;
    int kc = k >> 5, seg0 = (k >> 3) & 3, klow = k & 7;
#pragma unroll
    for (int half = 0; half < 2; half++) {
      int m = b * TQ + row0 + half * 8;
      float v0 = y[nf][half * 2] * (half ? i1 : i0);
      float v1 = y[nf][half * 2 + 1] * (half ? i1 : i0);
      int r = m & 127, mb2 = m >> 7;
      size_t t = ((size_t)mb2 * 32 + kc) * 4096 + (size_t)r * 32 +
                 ((seg0 ^ ((r >> 1) & 3)) << 3) + klow;
      uint32_t hi, lo;
      pack_hilo(v0, v1, hi, lo);
      *(uint32_t*)(Yh + t) = hi;
      *(uint32_t*)(Yl + t) = lo;
    }
  }
}

// ---------------------------------------------------------------------------
extern "C" void kernel_launch(void* const* d_in, const int* in_sizes, int n_in,
                              void* d_out, int out_size) {
  const float* query     = (const float*)d_in[0];
  const float* key_value = (const float*)d_in[1];
  const float* imp       = (const float*)d_in[2];
  const float* Wq        = (const float*)d_in[3];
  const float* Wk        = (const float*)d_in[4];
  const float* Wv        = (const float*)d_in[5];
  const float* Wo        = (const float*)d_in[6];
  float* out = (float*)d_out;

  __nv_bfloat16 *qh, *ql, *kvh, *kvl, *yh, *yl, *wh, *wl, *kfh, *kfl, *vth, *vtl;
  cudaGetSymbolAddress((void**)&qh, g_qh);
  cudaGetSymbolAddress((void**)&ql, g_ql);
  cudaGetSymbolAddress((void**)&kvh, g_kvh);
  cudaGetSymbolAddress((void**)&kvl, g_kvl);
  cudaGetSymbolAddress((void**)&yh, g_yh);
  cudaGetSymbolAddress((void**)&yl, g_yl);
  cudaGetSymbolAddress((void**)&wh, g_wh);
  cudaGetSymbolAddress((void**)&wl, g_wl);
  cudaGetSymbolAddress((void**)&kfh, g_kfh);
  cudaGetSymbolAddress((void**)&kfl, g_kfl);
  cudaGetSymbolAddress((void**)&vth, g_vth);
  cudaGetSymbolAddress((void**)&vtl, g_vtl);
  const size_t WSZ = (size_t)D_MODEL * D_MODEL;

  cudaFuncSetAttribute(proj_fused,
                       cudaFuncAttributeMaxDynamicSharedMemorySize, GS_SMEM);
  cudaFuncSetAttribute(gemm_out,
                       cudaFuncAttributeMaxDynamicSharedMemorySize, GS_SMEM);
  cudaFuncSetAttribute(flash_bulk,
                       cudaFuncAttributeMaxDynamicSharedMemorySize, FS_SMEM);

  // 1) Pack everything (query + kv + 4 weights) in one launch.
  const int total8 = NQ8 + NKV8 + 4 * NW8;   // 2097152
  pack_all<<<total8 / 256, 256>>>(query, key_value, Wq, Wk, Wv, Wo,
                                  qh, ql, kvh, kvl, wh, wl);

  // 2) Q/K/V projections fused into a single 1280-CTA launch.
  proj_fused<<<1280, 256, GS_SMEM>>>(qh, ql, kvh, kvl, wh, wl,
                                     yh, yl, kfh, kfl, vth, vtl);

  // 3) Flash attention -> Y packed as GEMM-A tiles (qh/ql reused).
  flash_bulk<<<dim3(TQ / 128, NHEADS, BATCH), 256, FS_SMEM>>>(
      yh, yl, kfh, kfl, vth, vtl, imp, qh, ql);

  // 4) Output projection -> fp32 out.
  gemm_out<<<dim3(8, 32), 256, GS_SMEM>>>(
      qh, ql, wh + 3 * WSZ, wl + 3 * WSZ, out, D_MODEL);
}